// round 1
// baseline (speedup 1.0000x reference)
#include <cuda_runtime.h>

#define NB 8
#define NC 256
#define ND 2048

// ---------------- static scratch (no allocations allowed) ----------------
__device__ float g_xt[NB * ND * NC];          // [b,d,c]  16.8 MB
__device__ float g_sq[NB * ND];               // ||xt_d||^2
__device__ float g_xf[NB * ND * NC];          // fc output 16.8 MB
__device__ float g_hg[(size_t)NB * ND * ND];  // incidence 128 MB (fp32 0/1)
__device__ float g_inv[NB * ND];              // 1/deg (0 if deg==0)
__device__ float g_E[NB * ND * NC];           // edge features 16.8 MB

// ---------------- transpose x[b,c,d] -> xt[b,d,c] ----------------
__global__ void k_transpose(const float* __restrict__ x) {
    __shared__ float tile[32][33];
    int b = blockIdx.z;
    int d0 = blockIdx.x * 32, c0 = blockIdx.y * 32;
    const float* xb = x + (size_t)b * NC * ND;
    float* xtb = g_xt + (size_t)b * ND * NC;
    int tx = threadIdx.x, ty = threadIdx.y;  // 32 x 8
#pragma unroll
    for (int i = 0; i < 32; i += 8)
        tile[ty + i][tx] = xb[(size_t)(c0 + ty + i) * ND + d0 + tx];
    __syncthreads();
#pragma unroll
    for (int i = 0; i < 32; i += 8)
        xtb[(size_t)(d0 + ty + i) * NC + c0 + tx] = tile[tx][ty + i];
}

// ---------------- sq[b,d] = sum_c xt^2 ----------------
__global__ void k_sq() {
    int row = blockIdx.x * 8 + (threadIdx.x >> 5);  // b*ND+d
    int lane = threadIdx.x & 31;
    const float* p = g_xt + (size_t)row * NC;
    float s = 0.f;
    for (int i = lane; i < NC; i += 32) {
        float v = p[i];
        s += v * v;
    }
#pragma unroll
    for (int o = 16; o > 0; o >>= 1) s += __shfl_xor_sync(0xFFFFFFFFu, s, o);
    if (lane == 0) g_sq[row] = s;
}

// ---------------- fc: xf[m][n] = sum_k xt[m][k] * W[n][k] + bias[n] (NT) ----------------
__global__ void __launch_bounds__(256) k_fc(const float* __restrict__ W,
                                            const float* __restrict__ bias) {
    int m0 = blockIdx.y * 64, n0 = blockIdx.x * 64;
    __shared__ float As[16][64];
    __shared__ float Bs[16][64];
    int tid = threadIdx.x;
    int tx = tid & 15, ty = tid >> 4;
    int lm = tid >> 2, lk = (tid & 3) << 2;
    float acc[4][4] = {};
    for (int k0 = 0; k0 < NC; k0 += 16) {
        float4 a = *(const float4*)(g_xt + (size_t)(m0 + lm) * NC + k0 + lk);
        As[lk + 0][lm] = a.x; As[lk + 1][lm] = a.y; As[lk + 2][lm] = a.z; As[lk + 3][lm] = a.w;
        float4 bb = *(const float4*)(W + (size_t)(n0 + lm) * NC + k0 + lk);
        Bs[lk + 0][lm] = bb.x; Bs[lk + 1][lm] = bb.y; Bs[lk + 2][lm] = bb.z; Bs[lk + 3][lm] = bb.w;
        __syncthreads();
#pragma unroll
        for (int k = 0; k < 16; k++) {
            float4 av = *(const float4*)&As[k][ty << 2];
            float4 bv = *(const float4*)&Bs[k][tx << 2];
            float am[4] = {av.x, av.y, av.z, av.w};
            float bn[4] = {bv.x, bv.y, bv.z, bv.w};
#pragma unroll
            for (int i = 0; i < 4; i++)
#pragma unroll
                for (int j = 0; j < 4; j++) acc[i][j] += am[i] * bn[j];
        }
        __syncthreads();
    }
#pragma unroll
    for (int i = 0; i < 4; i++) {
        int m = m0 + (ty << 2) + i;
        int n = n0 + (tx << 2);
        float4 o;
        o.x = acc[i][0] + bias[n + 0];
        o.y = acc[i][1] + bias[n + 1];
        o.z = acc[i][2] + bias[n + 2];
        o.w = acc[i][3] + bias[n + 3];
        *(float4*)(g_xf + (size_t)m * NC + n) = o;
    }
}

// ---------------- Gram + threshold: hg[i][j] = (sq_i+sq_j-2*dot < 484) ----------------
__global__ void __launch_bounds__(256) k_gram() {
    int b = blockIdx.z;
    const float* Ab = g_xt + (size_t)b * ND * NC;
    const float* sqb = g_sq + b * ND;
    float* Hb = g_hg + (size_t)b * ND * ND;
    int m0 = blockIdx.y * 64, n0 = blockIdx.x * 64;
    __shared__ float As[16][64];
    __shared__ float Bs[16][64];
    int tid = threadIdx.x;
    int tx = tid & 15, ty = tid >> 4;
    int lm = tid >> 2, lk = (tid & 3) << 2;
    float acc[4][4] = {};
    for (int k0 = 0; k0 < NC; k0 += 16) {
        float4 a = *(const float4*)(Ab + (size_t)(m0 + lm) * NC + k0 + lk);
        As[lk + 0][lm] = a.x; As[lk + 1][lm] = a.y; As[lk + 2][lm] = a.z; As[lk + 3][lm] = a.w;
        float4 bb = *(const float4*)(Ab + (size_t)(n0 + lm) * NC + k0 + lk);
        Bs[lk + 0][lm] = bb.x; Bs[lk + 1][lm] = bb.y; Bs[lk + 2][lm] = bb.z; Bs[lk + 3][lm] = bb.w;
        __syncthreads();
#pragma unroll
        for (int k = 0; k < 16; k++) {
            float4 av = *(const float4*)&As[k][ty << 2];
            float4 bv = *(const float4*)&Bs[k][tx << 2];
            float am[4] = {av.x, av.y, av.z, av.w};
            float bn[4] = {bv.x, bv.y, bv.z, bv.w};
#pragma unroll
            for (int i = 0; i < 4; i++)
#pragma unroll
                for (int j = 0; j < 4; j++) acc[i][j] += am[i] * bn[j];
        }
        __syncthreads();
    }
    int n = n0 + (tx << 2);
    float sn0 = sqb[n + 0], sn1 = sqb[n + 1], sn2 = sqb[n + 2], sn3 = sqb[n + 3];
#pragma unroll
    for (int i = 0; i < 4; i++) {
        int m = m0 + (ty << 2) + i;
        float sm = sqb[m];
        float4 h;
        h.x = (sm + sn0 - 2.f * acc[i][0] < 484.f) ? 1.f : 0.f;
        h.y = (sm + sn1 - 2.f * acc[i][1] < 484.f) ? 1.f : 0.f;
        h.z = (sm + sn2 - 2.f * acc[i][2] < 484.f) ? 1.f : 0.f;
        h.w = (sm + sn3 - 2.f * acc[i][3] < 484.f) ? 1.f : 0.f;
        *(float4*)(Hb + (size_t)m * ND + n) = h;
    }
}

// ---------------- inv-degree: g_inv[r] = 1/rowsum(hg[r]) ----------------
__global__ void __launch_bounds__(256) k_deg() {
    int row = blockIdx.x;  // b*ND + i
    const float* p = g_hg + (size_t)row * ND;
    float s = 0.f;
    for (int i = threadIdx.x; i < ND; i += 256) s += p[i];
    __shared__ float red[256];
    red[threadIdx.x] = s;
    __syncthreads();
    for (int o = 128; o > 0; o >>= 1) {
        if (threadIdx.x < o) red[threadIdx.x] += red[threadIdx.x + o];
        __syncthreads();
    }
    if (threadIdx.x == 0) g_inv[row] = (red[0] > 0.f) ? (1.f / red[0]) : 0.f;
}

// ---------------- aggregation: out = diag(inv) * hg @ Bsrc (NN GEMM) ----------------
// FINAL=false: Bsrc=g_xf -> g_E.   FINAL=true: Bsrc=g_E -> d_out (transposed) + residual xt.
template <bool FINAL>
__global__ void __launch_bounds__(256) k_agg(float* __restrict__ out) {
    int b = blockIdx.z;
    const float* Ab = g_hg + (size_t)b * ND * ND;
    const float* Bb = (FINAL ? g_E : g_xf) + (size_t)b * ND * NC;
    const float* invb = g_inv + b * ND;
    int m0 = blockIdx.y * 64, n0 = blockIdx.x * 64;
    __shared__ float As[16][64];
    __shared__ float Bs[16][64];
    int tid = threadIdx.x;
    int tx = tid & 15, ty = tid >> 4;
    int lmA = tid >> 2, lkA = (tid & 3) << 2;
    int lkB = tid >> 4, lnB = (tid & 15) << 2;
    float acc[4][4] = {};
    for (int k0 = 0; k0 < ND; k0 += 16) {
        float4 a = *(const float4*)(Ab + (size_t)(m0 + lmA) * ND + k0 + lkA);
        As[lkA + 0][lmA] = a.x; As[lkA + 1][lmA] = a.y; As[lkA + 2][lmA] = a.z; As[lkA + 3][lmA] = a.w;
        float4 bb = *(const float4*)(Bb + (size_t)(k0 + lkB) * NC + n0 + lnB);
        *(float4*)&Bs[lkB][lnB] = bb;
        __syncthreads();
#pragma unroll
        for (int k = 0; k < 16; k++) {
            float4 av = *(const float4*)&As[k][ty << 2];
            float4 bv = *(const float4*)&Bs[k][tx << 2];
            float am[4] = {av.x, av.y, av.z, av.w};
            float bn[4] = {bv.x, bv.y, bv.z, bv.w};
#pragma unroll
            for (int i = 0; i < 4; i++)
#pragma unroll
                for (int j = 0; j < 4; j++) acc[i][j] += am[i] * bn[j];
        }
        __syncthreads();
    }
    if (!FINAL) {
#pragma unroll
        for (int i = 0; i < 4; i++) {
            int m = m0 + (ty << 2) + i;
            float inv = invb[m];
            int n = n0 + (tx << 2);
            float4 o;
            o.x = inv * acc[i][0];
            o.y = inv * acc[i][1];
            o.z = inv * acc[i][2];
            o.w = inv * acc[i][3];
            *(float4*)(g_E + (size_t)b * ND * NC + (size_t)m * NC + n) = o;
        }
    } else {
        const float* xtb = g_xt + (size_t)b * ND * NC;
        float* ob = out + (size_t)b * NC * ND;
        int m = m0 + (ty << 2);
        float i0 = invb[m + 0], i1 = invb[m + 1], i2 = invb[m + 2], i3 = invb[m + 3];
#pragma unroll
        for (int j = 0; j < 4; j++) {
            int n = n0 + (tx << 2) + j;
            float4 o;
            o.x = i0 * acc[0][j] + xtb[(size_t)(m + 0) * NC + n];
            o.y = i1 * acc[1][j] + xtb[(size_t)(m + 1) * NC + n];
            o.z = i2 * acc[2][j] + xtb[(size_t)(m + 2) * NC + n];
            o.w = i3 * acc[3][j] + xtb[(size_t)(m + 3) * NC + n];
            *(float4*)(ob + (size_t)n * ND + m) = o;
        }
    }
}

// ---------------- LayerNorm(d) + SiLU, in-place on d_out rows ----------------
__global__ void __launch_bounds__(256) k_ln(float* __restrict__ out,
                                            const float* __restrict__ gamma,
                                            const float* __restrict__ beta) {
    int row = blockIdx.x;  // b*NC + c
    float* p = out + (size_t)row * ND;
    int t = threadIdx.x;
    float4 v0 = *(float4*)(p + t * 8);
    float4 v1 = *(float4*)(p + t * 8 + 4);
    float vals[8] = {v0.x, v0.y, v0.z, v0.w, v1.x, v1.y, v1.z, v1.w};
    float s = 0.f, s2 = 0.f;
#pragma unroll
    for (int u = 0; u < 8; u++) {
        s += vals[u];
        s2 += vals[u] * vals[u];
    }
    __shared__ float r1[256];
    __shared__ float r2[256];
    r1[t] = s;
    r2[t] = s2;
    __syncthreads();
    for (int o = 128; o > 0; o >>= 1) {
        if (t < o) {
            r1[t] += r1[t + o];
            r2[t] += r2[t + o];
        }
        __syncthreads();
    }
    float mean = r1[0] * (1.f / ND);
    float var = r2[0] * (1.f / ND) - mean * mean;
    float rstd = rsqrtf(var + 1e-5f);
#pragma unroll
    for (int u = 0; u < 8; u++) {
        int d = t * 8 + u;
        float yn = (vals[u] - mean) * rstd * gamma[d] + beta[d];
        vals[u] = yn / (1.f + expf(-yn));
    }
    v0.x = vals[0]; v0.y = vals[1]; v0.z = vals[2]; v0.w = vals[3];
    v1.x = vals[4]; v1.y = vals[5]; v1.z = vals[6]; v1.w = vals[7];
    *(float4*)(p + t * 8) = v0;
    *(float4*)(p + t * 8 + 4) = v1;
}

// ---------------- launch ----------------
extern "C" void kernel_launch(void* const* d_in, const int* in_sizes, int n_in,
                              void* d_out, int out_size) {
    const float* x = (const float*)d_in[0];
    const float* W = (const float*)d_in[1];
    const float* bias = (const float*)d_in[2];
    const float* gamma = (const float*)d_in[3];
    const float* beta = (const float*)d_in[4];
    float* out = (float*)d_out;

    (void)in_sizes; (void)n_in; (void)out_size;

    dim3 bt(32, 8);
    dim3 gt(ND / 32, NC / 32, NB);
    k_transpose<<<gt, bt>>>(x);
    k_sq<<<NB * ND / 8, 256>>>();
    k_fc<<<dim3(NC / 64, (NB * ND) / 64), 256>>>(W, bias);
    k_gram<<<dim3(ND / 64, ND / 64, NB), 256>>>();
    k_deg<<<NB * ND, 256>>>();
    k_agg<false><<<dim3(NC / 64, ND / 64, NB), 256>>>(nullptr);
    k_agg<true><<<dim3(NC / 64, ND / 64, NB), 256>>>(out);
    k_ln<<<NB * NC, 256>>>(out, gamma, beta);
}

// round 4
// speedup vs baseline: 3.5522x; 3.5522x over previous
#include <cuda_runtime.h>
#include <cuda_bf16.h>
#include <cstdint>

#define NB 8
#define NC 256
#define ND 2048
typedef __nv_bfloat16 bf16;

// ---------------- static scratch ----------------
__device__ __align__(128) bf16  g_xthi[NB * ND * NC];
__device__ __align__(128) bf16  g_xtlo[NB * ND * NC];
__device__ __align__(128) float g_sq[NB * ND];
__device__ __align__(128) bf16  g_whi[NC * NC];
__device__ __align__(128) bf16  g_wlo[NC * NC];
__device__ __align__(128) bf16  g_xfhi[NB * NC * ND];   // [b][o][d]
__device__ __align__(128) bf16  g_xflo[NB * NC * ND];
__device__ __align__(128) bf16  g_hg[(size_t)NB * ND * ND];
__device__ __align__(128) float g_inv[NB * ND];
__device__ __align__(128) bf16  g_Ehi[NB * NC * ND];    // [b][o][d]
__device__ __align__(128) bf16  g_Elo[NB * NC * ND];

// ---------------- helpers ----------------
__device__ __forceinline__ uint32_t smem_u32(const void* p) {
    uint32_t a;
    asm("{ .reg .u64 t; cvta.to.shared.u64 t, %1; cvt.u32.u64 %0, t; }" : "=r"(a) : "l"(p));
    return a;
}
#define SW128(x) ((x) ^ (((x) >> 3) & 0x70))

__device__ __forceinline__ void cp16(uint32_t dst, const void* src) {
    asm volatile("cp.async.cg.shared.global [%0], [%1], 16;\n" :: "r"(dst), "l"(src));
}
__device__ __forceinline__ void cpa_commit() { asm volatile("cp.async.commit_group;\n" ::: "memory"); }
__device__ __forceinline__ void cpa_wait0() { asm volatile("cp.async.wait_group 0;\n" ::: "memory"); }
__device__ __forceinline__ void cpa_wait1() { asm volatile("cp.async.wait_group 1;\n" ::: "memory"); }

__device__ __forceinline__ void ldm4(uint32_t* r, uint32_t addr) {
    asm volatile("ldmatrix.sync.aligned.m8n8.x4.shared.b16 {%0,%1,%2,%3}, [%4];"
                 : "=r"(r[0]), "=r"(r[1]), "=r"(r[2]), "=r"(r[3]) : "r"(addr));
}
__device__ __forceinline__ void mma16816(float* d, const uint32_t* a, const uint32_t* b) {
    asm volatile(
        "mma.sync.aligned.m16n8k16.row.col.f32.bf16.bf16.f32 "
        "{%0,%1,%2,%3}, {%4,%5,%6,%7}, {%8,%9}, {%0,%1,%2,%3};"
        : "+f"(d[0]), "+f"(d[1]), "+f"(d[2]), "+f"(d[3])
        : "r"(a[0]), "r"(a[1]), "r"(a[2]), "r"(a[3]), "r"(b[0]), "r"(b[1]));
}
__device__ __forceinline__ uint32_t pk2(bf16 a, bf16 b) {
    return (uint32_t)__bfloat16_as_ushort(a) | ((uint32_t)__bfloat16_as_ushort(b) << 16);
}

// load one 128-row x 64-col bf16 chunk into SW128 smem tile (256 threads)
__device__ __forceinline__ void load_tile256(uint32_t tb, const bf16* g, size_t rs, int kc, int t) {
#pragma unroll
    for (int i = 0; i < 4; i++) {
        int lin = i * 256 + t;
        int row = lin >> 3, seg = lin & 7;
        cp16(tb + SW128(row * 128 + seg * 16), g + (size_t)row * rs + kc + seg * 8);
    }
}

// ---------------- block GEMM mainloop ----------------
// Computes 128x128 tile: acc[f][nt][j] over K, A tiles {A0[,A1]}, B tiles {B0[,B1]}.
// Combos: all (pa,pb) except (1,1) [lo*lo dropped].
template <int NA, int NBt>
__device__ __forceinline__ void gemm_main(
    uint32_t sb, const bf16* A0, const bf16* A1, const bf16* B0, const bf16* B1,
    size_t sA, size_t sB, int nchunks, float acc[2][8][4])
{
    const uint32_t TS = 16384u;
    const uint32_t STAGE = (NA + NBt) * TS;
    int t = threadIdx.x;
    int lane = t & 31, wid = t >> 5;
    int warp_m = (wid & 3) * 32, warp_n = (wid >> 2) * 64;
    int lrow = lane & 15;
    int lcol = (lane & 16) ? 16 : 0;

    // prologue: chunk 0 -> stage 0
    {
        load_tile256(sb + 0 * TS, A0, sA, 0, t);
        if (NA == 2) load_tile256(sb + 1 * TS, A1, sA, 0, t);
        load_tile256(sb + NA * TS, B0, sB, 0, t);
        if (NBt == 2) load_tile256(sb + (NA + 1) * TS, B1, sB, 0, t);
        cpa_commit();
    }
    for (int c = 0; c < nchunks; c++) {
        uint32_t cur = sb + (uint32_t)(c & 1) * STAGE;
        if (c + 1 < nchunks) {
            uint32_t nxt = sb + (uint32_t)((c + 1) & 1) * STAGE;
            int kc = (c + 1) * 64;
            load_tile256(nxt + 0 * TS, A0, sA, kc, t);
            if (NA == 2) load_tile256(nxt + 1 * TS, A1, sA, kc, t);
            load_tile256(nxt + NA * TS, B0, sB, kc, t);
            if (NBt == 2) load_tile256(nxt + (NA + 1) * TS, B1, sB, kc, t);
            cpa_commit();
            cpa_wait1();
        } else {
            cpa_wait0();
        }
        __syncthreads();
#pragma unroll
        for (int ks = 0; ks < 4; ks++) {
            int kb = ks * 32 + lcol;  // byte column within 128B row
            uint32_t a[NA][2][4];
#pragma unroll
            for (int v = 0; v < NA; v++)
#pragma unroll
                for (int f = 0; f < 2; f++)
                    ldm4(a[v][f], cur + v * TS + SW128((warp_m + f * 16 + lrow) * 128 + kb));
            uint32_t bfr[NBt][8][2];
#pragma unroll
            for (int v = 0; v < NBt; v++)
#pragma unroll
                for (int np = 0; np < 4; np++) {
                    uint32_t r[4];
                    ldm4(r, cur + (NA + v) * TS + SW128((warp_n + np * 16 + lrow) * 128 + kb));
                    bfr[v][2 * np][0] = r[0]; bfr[v][2 * np][1] = r[2];
                    bfr[v][2 * np + 1][0] = r[1]; bfr[v][2 * np + 1][1] = r[3];
                }
#pragma unroll
            for (int pa = 0; pa < NA; pa++)
#pragma unroll
                for (int pb = 0; pb < NBt; pb++) {
                    if (pa == 1 && pb == 1) continue;
#pragma unroll
                    for (int f = 0; f < 2; f++)
#pragma unroll
                        for (int nt = 0; nt < 8; nt++)
                            mma16816(acc[f][nt], a[pa][f], bfr[pb][nt]);
                }
        }
        __syncthreads();
    }
}

// ---------------- GEMM kernels ----------------
// Gram + threshold: hg[m][n] = (sq_m + sq_n - 2*dot < 484)
__global__ void __launch_bounds__(256) k_gram_mma() {
    extern __shared__ char smem[];
    uint32_t sb = smem_u32(smem);
    int b = blockIdx.z, m0 = blockIdx.y * 128, n0 = blockIdx.x * 128;
    const bf16* Xh = g_xthi + (size_t)b * ND * NC;
    const bf16* Xl = g_xtlo + (size_t)b * ND * NC;
    float acc[2][8][4] = {};
    gemm_main<2, 2>(sb, Xh + (size_t)m0 * NC, Xl + (size_t)m0 * NC,
                    Xh + (size_t)n0 * NC, Xl + (size_t)n0 * NC, NC, NC, NC / 64, acc);

    float* s_sqm = (float*)smem;
    float* s_sqn = s_sqm + 128;
    int t = threadIdx.x;
    if (t < 128) s_sqm[t] = g_sq[b * ND + m0 + t];
    else s_sqn[t - 128] = g_sq[b * ND + n0 + (t - 128)];
    __syncthreads();

    int lane = t & 31, wid = t >> 5;
    int warp_m = (wid & 3) * 32, warp_n = (wid >> 2) * 64;
    int r4 = lane >> 2, c2 = (lane & 3) * 2;
    bf16* Hb = g_hg + (size_t)b * ND * ND;
    const bf16 one = __float2bfloat16(1.f), zero = __float2bfloat16(0.f);
#pragma unroll
    for (int f = 0; f < 2; f++)
#pragma unroll
        for (int h = 0; h < 2; h++) {
            int m = warp_m + f * 16 + r4 + h * 8;
            float sm = s_sqm[m];
            uint32_t* hrow = (uint32_t*)(Hb + (size_t)(m0 + m) * ND + n0);
#pragma unroll
            for (int nt = 0; nt < 8; nt++) {
                int n = warp_n + nt * 8 + c2;
                float d0 = sm + s_sqn[n] - 2.f * acc[f][nt][2 * h];
                float d1 = sm + s_sqn[n + 1] - 2.f * acc[f][nt][2 * h + 1];
                hrow[n >> 1] = pk2(d0 < 484.f ? one : zero, d1 < 484.f ? one : zero);
            }
        }
}

// FC: xf_T[o][d] = sum_c W[o][c]*xt[d][c] + bias[o]  (split hi/lo)
__global__ void __launch_bounds__(256) k_fc_mma(const float* __restrict__ bias) {
    extern __shared__ char smem[];
    uint32_t sb = smem_u32(smem);
    int b = blockIdx.z, m0 = blockIdx.y * 128, n0 = blockIdx.x * 128;
    const bf16* Xh = g_xthi + (size_t)b * ND * NC;
    const bf16* Xl = g_xtlo + (size_t)b * ND * NC;
    float acc[2][8][4] = {};
    gemm_main<2, 2>(sb, g_whi + (size_t)m0 * NC, g_wlo + (size_t)m0 * NC,
                    Xh + (size_t)n0 * NC, Xl + (size_t)n0 * NC, NC, NC, NC / 64, acc);

    int t = threadIdx.x;
    int lane = t & 31, wid = t >> 5;
    int warp_m = (wid & 3) * 32, warp_n = (wid >> 2) * 64;
    int r4 = lane >> 2, c2 = (lane & 3) * 2;
#pragma unroll
    for (int f = 0; f < 2; f++)
#pragma unroll
        for (int h = 0; h < 2; h++) {
            int m = warp_m + f * 16 + r4 + h * 8;
            float bv = bias[m0 + m];
            uint32_t* rh = (uint32_t*)(g_xfhi + ((size_t)b * NC + m0 + m) * ND + n0);
            uint32_t* rl = (uint32_t*)(g_xflo + ((size_t)b * NC + m0 + m) * ND + n0);
#pragma unroll
            for (int nt = 0; nt < 8; nt++) {
                int n = warp_n + nt * 8 + c2;
                float v0 = acc[f][nt][2 * h] + bv;
                float v1 = acc[f][nt][2 * h + 1] + bv;
                bf16 h0 = __float2bfloat16(v0), h1 = __float2bfloat16(v1);
                bf16 l0 = __float2bfloat16(v0 - __bfloat162float(h0));
                bf16 l1 = __float2bfloat16(v1 - __bfloat162float(h1));
                rh[n >> 1] = pk2(h0, h1);
                rl[n >> 1] = pk2(l0, l1);
            }
        }
}

// AGG: D[o][n] = sum_k S[o][k]*hg[n][k];  scale by inv[n]; FINAL adds residual x.
template <bool FINAL>
__global__ void __launch_bounds__(256) k_agg_mma(const float* __restrict__ xres,
                                                 float* __restrict__ out) {
    extern __shared__ char smem[];
    uint32_t sb = smem_u32(smem);
    int b = blockIdx.z, m0 = blockIdx.y * 128, n0 = blockIdx.x * 128;
    const bf16* Sh = (FINAL ? g_Ehi : g_xfhi) + (size_t)b * NC * ND;
    const bf16* Sl = (FINAL ? g_Elo : g_xflo) + (size_t)b * NC * ND;
    const bf16* H = g_hg + (size_t)b * ND * ND;
    float acc[2][8][4] = {};
    gemm_main<2, 1>(sb, Sh + (size_t)m0 * ND, Sl + (size_t)m0 * ND,
                    H + (size_t)n0 * ND, nullptr, ND, ND, ND / 64, acc);

    float* s_inv = (float*)smem;
    int t = threadIdx.x;
    if (t < 128) s_inv[t] = g_inv[b * ND + n0 + t];
    __syncthreads();

    int lane = t & 31, wid = t >> 5;
    int warp_m = (wid & 3) * 32, warp_n = (wid >> 2) * 64;
    int r4 = lane >> 2, c2 = (lane & 3) * 2;
#pragma unroll
    for (int f = 0; f < 2; f++)
#pragma unroll
        for (int h = 0; h < 2; h++) {
            int m = warp_m + f * 16 + r4 + h * 8;
            if (!FINAL) {
                uint32_t* rh = (uint32_t*)(g_Ehi + ((size_t)b * NC + m0 + m) * ND + n0);
                uint32_t* rl = (uint32_t*)(g_Elo + ((size_t)b * NC + m0 + m) * ND + n0);
#pragma unroll
                for (int nt = 0; nt < 8; nt++) {
                    int n = warp_n + nt * 8 + c2;
                    float v0 = acc[f][nt][2 * h] * s_inv[n];
                    float v1 = acc[f][nt][2 * h + 1] * s_inv[n + 1];
                    bf16 h0 = __float2bfloat16(v0), h1 = __float2bfloat16(v1);
                    bf16 l0 = __float2bfloat16(v0 - __bfloat162float(h0));
                    bf16 l1 = __float2bfloat16(v1 - __bfloat162float(h1));
                    rh[n >> 1] = pk2(h0, h1);
                    rl[n >> 1] = pk2(l0, l1);
                }
            } else {
                const float* xrow = xres + ((size_t)b * NC + m0 + m) * ND + n0;
                float* orow = out + ((size_t)b * NC + m0 + m) * ND + n0;
#pragma unroll
                for (int nt = 0; nt < 8; nt++) {
                    int n = warp_n + nt * 8 + c2;
                    float2 xv = *(const float2*)(xrow + n);
                    float2 o;
                    o.x = acc[f][nt][2 * h] * s_inv[n] + xv.x;
                    o.y = acc[f][nt][2 * h + 1] * s_inv[n + 1] + xv.y;
                    *(float2*)(orow + n) = o;
                }
            }
        }
}

// ---------------- prep / small kernels ----------------
__global__ void k_prep_xt(const float* __restrict__ x) {
    __shared__ float tile[32][33];
    int b = blockIdx.z;
    int d0 = blockIdx.x * 32, c0 = blockIdx.y * 32;
    const float* xb = x + (size_t)b * NC * ND;
    int tx = threadIdx.x, ty = threadIdx.y;  // 32x8
#pragma unroll
    for (int i = 0; i < 32; i += 8)
        tile[ty + i][tx] = xb[(size_t)(c0 + ty + i) * ND + d0 + tx];
    __syncthreads();
    bf16* oh = g_xthi + (size_t)b * ND * NC;
    bf16* ol = g_xtlo + (size_t)b * ND * NC;
#pragma unroll
    for (int i = 0; i < 32; i += 8) {
        float v = tile[tx][ty + i];
        bf16 h = __float2bfloat16(v);
        bf16 l = __float2bfloat16(v - __bfloat162float(h));
        size_t idx = (size_t)(d0 + ty + i) * NC + c0 + tx;
        oh[idx] = h;
        ol[idx] = l;
    }
}

__global__ void __launch_bounds__(256) k_sq(const float* __restrict__ x) {
    int gid = blockIdx.x * 256 + threadIdx.x;  // b*ND + d
    int b = gid >> 11, d = gid & (ND - 1);
    const float* xb = x + (size_t)b * NC * ND + d;
    float s = 0.f;
#pragma unroll 8
    for (int c = 0; c < NC; c++) {
        float v = xb[(size_t)c * ND];
        s += v * v;
    }
    g_sq[gid] = s;
}

__global__ void __launch_bounds__(256) k_prep_w(const float* __restrict__ W) {
    int i = blockIdx.x * 256 + threadIdx.x;
    float v = W[i];
    bf16 h = __float2bfloat16(v);
    g_whi[i] = h;
    g_wlo[i] = __float2bfloat16(v - __bfloat162float(h));
}

__global__ void __launch_bounds__(256) k_deg() {
    size_t row = blockIdx.x;
    const bf16* p = g_hg + row * ND;
    int t = threadIdx.x;
    uint4 v = *(const uint4*)(p + t * 8);
    float s = 0.f;
    uint32_t u[4] = {v.x, v.y, v.z, v.w};
#pragma unroll
    for (int i = 0; i < 4; i++) {
        float2 f = __bfloat1622float2(*(__nv_bfloat162*)&u[i]);
        s += f.x + f.y;
    }
    __shared__ float red[256];
    red[t] = s;
    __syncthreads();
    for (int o = 128; o > 0; o >>= 1) {
        if (t < o) red[t] += red[t + o];
        __syncthreads();
    }
    if (t == 0) g_inv[row] = (red[0] > 0.f) ? (1.f / red[0]) : 0.f;
}

__global__ void __launch_bounds__(256) k_ln(float* __restrict__ out,
                                            const float* __restrict__ gamma,
                                            const float* __restrict__ beta) {
    int row = blockIdx.x;  // b*NC + c
    float* p = out + (size_t)row * ND;
    int t = threadIdx.x;
    float4 v0 = *(float4*)(p + t * 8);
    float4 v1 = *(float4*)(p + t * 8 + 4);
    float vals[8] = {v0.x, v0.y, v0.z, v0.w, v1.x, v1.y, v1.z, v1.w};
    float s = 0.f, s2 = 0.f;
#pragma unroll
    for (int u = 0; u < 8; u++) {
        s += vals[u];
        s2 += vals[u] * vals[u];
    }
    __shared__ float r1[256];
    __shared__ float r2[256];
    r1[t] = s;
    r2[t] = s2;
    __syncthreads();
    for (int o = 128; o > 0; o >>= 1) {
        if (t < o) {
            r1[t] += r1[t + o];
            r2[t] += r2[t + o];
        }
        __syncthreads();
    }
    float mean = r1[0] * (1.f / ND);
    float var = r2[0] * (1.f / ND) - mean * mean;
    float rstd = rsqrtf(var + 1e-5f);
#pragma unroll
    for (int u = 0; u < 8; u++) {
        int d = t * 8 + u;
        float yn = (vals[u] - mean) * rstd * gamma[d] + beta[d];
        vals[u] = yn / (1.f + expf(-yn));
    }
    v0.x = vals[0]; v0.y = vals[1]; v0.z = vals[2]; v0.w = vals[3];
    v1.x = vals[4]; v1.y = vals[5]; v1.z = vals[6]; v1.w = vals[7];
    *(float4*)(p + t * 8) = v0;
    *(float4*)(p + t * 8 + 4) = v1;
}

// ---------------- launch ----------------
extern "C" void kernel_launch(void* const* d_in, const int* in_sizes, int n_in,
                              void* d_out, int out_size) {
    const float* x = (const float*)d_in[0];
    const float* W = (const float*)d_in[1];
    const float* bias = (const float*)d_in[2];
    const float* gamma = (const float*)d_in[3];
    const float* beta = (const float*)d_in[4];
    float* out = (float*)d_out;
    (void)in_sizes; (void)n_in; (void)out_size;

    const int SMEM_4 = 2 * 4 * 16384;  // 131072 (gram, fc)
    const int SMEM_3 = 2 * 3 * 16384;  // 98304  (agg)
    static bool attr_set = false;
    if (!attr_set) {
        cudaFuncSetAttribute(k_gram_mma, cudaFuncAttributeMaxDynamicSharedMemorySize, SMEM_4);
        cudaFuncSetAttribute(k_fc_mma, cudaFuncAttributeMaxDynamicSharedMemorySize, SMEM_4);
        cudaFuncSetAttribute(k_agg_mma<false>, cudaFuncAttributeMaxDynamicSharedMemorySize, SMEM_3);
        cudaFuncSetAttribute(k_agg_mma<true>, cudaFuncAttributeMaxDynamicSharedMemorySize, SMEM_3);
        attr_set = true;
    }

    k_prep_xt<<<dim3(ND / 32, NC / 32, NB), dim3(32, 8)>>>(x);
    k_sq<<<NB * ND / 256, 256>>>(x);
    k_prep_w<<<NC * NC / 256, 256>>>(W);
    k_fc_mma<<<dim3(ND / 128, NC / 128, NB), 256, SMEM_4>>>(bias);
    k_gram_mma<<<dim3(ND / 128, ND / 128, NB), 256, SMEM_4>>>();
    k_deg<<<NB * ND, 256>>>();
    k_agg_mma<false><<<dim3(ND / 128, NC / 128, NB), 256, SMEM_3>>>(nullptr, nullptr);
    k_agg_mma<true><<<dim3(ND / 128, NC / 128, NB), 256, SMEM_3>>>(x, out);
    k_ln<<<NB * NC, 256>>>(out, gamma, beta);
}

// round 5
// speedup vs baseline: 3.5584x; 1.0017x over previous
#include <cuda_runtime.h>
#include <cuda_bf16.h>
#include <cstdint>

#define NB 8
#define NC 256
#define ND 2048
typedef __nv_bfloat16 bf16;

// ---------------- static scratch ----------------
__device__ __align__(128) bf16  g_xthi[NB * ND * NC];
__device__ __align__(128) bf16  g_xtlo[NB * ND * NC];
__device__ __align__(128) float g_sq[NB * ND];
__device__ __align__(128) bf16  g_whi[NC * NC];
__device__ __align__(128) bf16  g_wlo[NC * NC];
__device__ __align__(128) bf16  g_xfhi[NB * NC * ND];   // [b][o][d]
__device__ __align__(128) bf16  g_xflo[NB * NC * ND];
__device__ __align__(128) bf16  g_hg[(size_t)NB * ND * ND];
__device__ __align__(128) float g_inv[NB * ND];
__device__ __align__(128) bf16  g_Ehi[NB * NC * ND];    // [b][o][d]
__device__ __align__(128) bf16  g_Elo[NB * NC * ND];

// ---------------- helpers ----------------
__device__ __forceinline__ uint32_t smem_u32(const void* p) {
    uint32_t a;
    asm("{ .reg .u64 t; cvta.to.shared.u64 t, %1; cvt.u32.u64 %0, t; }" : "=r"(a) : "l"(p));
    return a;
}
#define SW128(x) ((x) ^ (((x) >> 3) & 0x70))

__device__ __forceinline__ void cp16(uint32_t dst, const void* src) {
    asm volatile("cp.async.cg.shared.global [%0], [%1], 16;\n" :: "r"(dst), "l"(src));
}
__device__ __forceinline__ void cpa_commit() { asm volatile("cp.async.commit_group;\n" ::: "memory"); }
__device__ __forceinline__ void cpa_wait0() { asm volatile("cp.async.wait_group 0;\n" ::: "memory"); }
__device__ __forceinline__ void cpa_wait1() { asm volatile("cp.async.wait_group 1;\n" ::: "memory"); }

__device__ __forceinline__ void ldm4(uint32_t* r, uint32_t addr) {
    asm volatile("ldmatrix.sync.aligned.m8n8.x4.shared.b16 {%0,%1,%2,%3}, [%4];"
                 : "=r"(r[0]), "=r"(r[1]), "=r"(r[2]), "=r"(r[3]) : "r"(addr));
}
__device__ __forceinline__ void mma16816(float* d, const uint32_t* a, const uint32_t* b) {
    asm volatile(
        "mma.sync.aligned.m16n8k16.row.col.f32.bf16.bf16.f32 "
        "{%0,%1,%2,%3}, {%4,%5,%6,%7}, {%8,%9}, {%0,%1,%2,%3};"
        : "+f"(d[0]), "+f"(d[1]), "+f"(d[2]), "+f"(d[3])
        : "r"(a[0]), "r"(a[1]), "r"(a[2]), "r"(a[3]), "r"(b[0]), "r"(b[1]));
}
__device__ __forceinline__ uint32_t pk2(bf16 a, bf16 b) {
    return (uint32_t)__bfloat16_as_ushort(a) | ((uint32_t)__bfloat16_as_ushort(b) << 16);
}

// load one 128-row x 64-col bf16 chunk into SW128 smem tile (256 threads)
__device__ __forceinline__ void load_tile256(uint32_t tb, const bf16* g, size_t rs, int kc, int t) {
#pragma unroll
    for (int i = 0; i < 4; i++) {
        int lin = i * 256 + t;
        int row = lin >> 3, seg = lin & 7;
        cp16(tb + SW128(row * 128 + seg * 16), g + (size_t)row * rs + kc + seg * 8);
    }
}

// ---------------- block GEMM mainloop ----------------
// Computes 128x128 tile: acc[f][nt][j] over K, A tiles {A0[,A1]}, B tiles {B0[,B1]}.
// Combos: all (pa,pb) except (1,1) [lo*lo dropped].
template <int NA, int NBt>
__device__ __forceinline__ void gemm_main(
    uint32_t sb, const bf16* A0, const bf16* A1, const bf16* B0, const bf16* B1,
    size_t sA, size_t sB, int nchunks, float acc[2][8][4])
{
    const uint32_t TS = 16384u;
    const uint32_t STAGE = (NA + NBt) * TS;
    int t = threadIdx.x;
    int lane = t & 31, wid = t >> 5;
    int warp_m = (wid & 3) * 32, warp_n = (wid >> 2) * 64;
    int lrow = lane & 15;
    int lcol = (lane & 16) ? 16 : 0;

    // prologue: chunk 0 -> stage 0
    {
        load_tile256(sb + 0 * TS, A0, sA, 0, t);
        if (NA == 2) load_tile256(sb + 1 * TS, A1, sA, 0, t);
        load_tile256(sb + NA * TS, B0, sB, 0, t);
        if (NBt == 2) load_tile256(sb + (NA + 1) * TS, B1, sB, 0, t);
        cpa_commit();
    }
    for (int c = 0; c < nchunks; c++) {
        uint32_t cur = sb + (uint32_t)(c & 1) * STAGE;
        if (c + 1 < nchunks) {
            uint32_t nxt = sb + (uint32_t)((c + 1) & 1) * STAGE;
            int kc = (c + 1) * 64;
            load_tile256(nxt + 0 * TS, A0, sA, kc, t);
            if (NA == 2) load_tile256(nxt + 1 * TS, A1, sA, kc, t);
            load_tile256(nxt + NA * TS, B0, sB, kc, t);
            if (NBt == 2) load_tile256(nxt + (NA + 1) * TS, B1, sB, kc, t);
            cpa_commit();
            cpa_wait1();
        } else {
            cpa_wait0();
        }
        __syncthreads();
#pragma unroll
        for (int ks = 0; ks < 4; ks++) {
            int kb = ks * 32 + lcol;  // byte column within 128B row
            uint32_t a[NA][2][4];
#pragma unroll
            for (int v = 0; v < NA; v++)
#pragma unroll
                for (int f = 0; f < 2; f++)
                    ldm4(a[v][f], cur + v * TS + SW128((warp_m + f * 16 + lrow) * 128 + kb));
            uint32_t bfr[NBt][8][2];
#pragma unroll
            for (int v = 0; v < NBt; v++)
#pragma unroll
                for (int np = 0; np < 4; np++) {
                    uint32_t r[4];
                    ldm4(r, cur + (NA + v) * TS + SW128((warp_n + np * 16 + lrow) * 128 + kb));
                    bfr[v][2 * np][0] = r[0]; bfr[v][2 * np][1] = r[2];
                    bfr[v][2 * np + 1][0] = r[1]; bfr[v][2 * np + 1][1] = r[3];
                }
#pragma unroll
            for (int pa = 0; pa < NA; pa++)
#pragma unroll
                for (int pb = 0; pb < NBt; pb++) {
                    if (pa == 1 && pb == 1) continue;
#pragma unroll
                    for (int f = 0; f < 2; f++)
#pragma unroll
                        for (int nt = 0; nt < 8; nt++)
                            mma16816(acc[f][nt], a[pa][f], bfr[pb][nt]);
                }
        }
        __syncthreads();
    }
}

// ---------------- GEMM kernels ----------------
// Gram + threshold: hg[m][n] = (sq_m + sq_n - 2*dot < 484)
__global__ void __launch_bounds__(256) k_gram_mma() {
    extern __shared__ char smem[];
    uint32_t sb = smem_u32(smem);
    int b = blockIdx.z, m0 = blockIdx.y * 128, n0 = blockIdx.x * 128;
    const bf16* Xh = g_xthi + (size_t)b * ND * NC;
    const bf16* Xl = g_xtlo + (size_t)b * ND * NC;
    float acc[2][8][4] = {};
    gemm_main<2, 2>(sb, Xh + (size_t)m0 * NC, Xl + (size_t)m0 * NC,
                    Xh + (size_t)n0 * NC, Xl + (size_t)n0 * NC, NC, NC, NC / 64, acc);

    float* s_sqm = (float*)smem;
    float* s_sqn = s_sqm + 128;
    int t = threadIdx.x;
    if (t < 128) s_sqm[t] = g_sq[b * ND + m0 + t];
    else s_sqn[t - 128] = g_sq[b * ND + n0 + (t - 128)];
    __syncthreads();

    int lane = t & 31, wid = t >> 5;
    int warp_m = (wid & 3) * 32, warp_n = (wid >> 2) * 64;
    int r4 = lane >> 2, c2 = (lane & 3) * 2;
    bf16* Hb = g_hg + (size_t)b * ND * ND;
    const bf16 one = __float2bfloat16(1.f), zero = __float2bfloat16(0.f);
#pragma unroll
    for (int f = 0; f < 2; f++)
#pragma unroll
        for (int h = 0; h < 2; h++) {
            int m = warp_m + f * 16 + r4 + h * 8;
            float sm = s_sqm[m];
            uint32_t* hrow = (uint32_t*)(Hb + (size_t)(m0 + m) * ND + n0);
#pragma unroll
            for (int nt = 0; nt < 8; nt++) {
                int n = warp_n + nt * 8 + c2;
                float d0 = sm + s_sqn[n] - 2.f * acc[f][nt][2 * h];
                float d1 = sm + s_sqn[n + 1] - 2.f * acc[f][nt][2 * h + 1];
                hrow[n >> 1] = pk2(d0 < 484.f ? one : zero, d1 < 484.f ? one : zero);
            }
        }
}

// FC: xf_T[o][d] = sum_c W[o][c]*xt[d][c] + bias[o]  (split hi/lo)
__global__ void __launch_bounds__(256) k_fc_mma(const float* __restrict__ bias) {
    extern __shared__ char smem[];
    uint32_t sb = smem_u32(smem);
    int b = blockIdx.z, m0 = blockIdx.y * 128, n0 = blockIdx.x * 128;
    const bf16* Xh = g_xthi + (size_t)b * ND * NC;
    const bf16* Xl = g_xtlo + (size_t)b * ND * NC;
    float acc[2][8][4] = {};
    gemm_main<2, 2>(sb, g_whi + (size_t)m0 * NC, g_wlo + (size_t)m0 * NC,
                    Xh + (size_t)n0 * NC, Xl + (size_t)n0 * NC, NC, NC, NC / 64, acc);

    int t = threadIdx.x;
    int lane = t & 31, wid = t >> 5;
    int warp_m = (wid & 3) * 32, warp_n = (wid >> 2) * 64;
    int r4 = lane >> 2, c2 = (lane & 3) * 2;
#pragma unroll
    for (int f = 0; f < 2; f++)
#pragma unroll
        for (int h = 0; h < 2; h++) {
            int m = warp_m + f * 16 + r4 + h * 8;
            float bv = bias[m0 + m];
            uint32_t* rh = (uint32_t*)(g_xfhi + ((size_t)b * NC + m0 + m) * ND + n0);
            uint32_t* rl = (uint32_t*)(g_xflo + ((size_t)b * NC + m0 + m) * ND + n0);
#pragma unroll
            for (int nt = 0; nt < 8; nt++) {
                int n = warp_n + nt * 8 + c2;
                float v0 = acc[f][nt][2 * h] + bv;
                float v1 = acc[f][nt][2 * h + 1] + bv;
                bf16 h0 = __float2bfloat16(v0), h1 = __float2bfloat16(v1);
                bf16 l0 = __float2bfloat16(v0 - __bfloat162float(h0));
                bf16 l1 = __float2bfloat16(v1 - __bfloat162float(h1));
                rh[n >> 1] = pk2(h0, h1);
                rl[n >> 1] = pk2(l0, l1);
            }
        }
}

// AGG: D[o][n] = sum_k S[o][k]*hg[n][k];  scale by inv[n]; FINAL adds residual x.
template <bool FINAL>
__global__ void __launch_bounds__(256) k_agg_mma(const float* __restrict__ xres,
                                                 float* __restrict__ out) {
    extern __shared__ char smem[];
    uint32_t sb = smem_u32(smem);
    int b = blockIdx.z, m0 = blockIdx.y * 128, n0 = blockIdx.x * 128;
    const bf16* Sh = (FINAL ? g_Ehi : g_xfhi) + (size_t)b * NC * ND;
    const bf16* Sl = (FINAL ? g_Elo : g_xflo) + (size_t)b * NC * ND;
    const bf16* H = g_hg + (size_t)b * ND * ND;
    float acc[2][8][4] = {};
    gemm_main<2, 1>(sb, Sh + (size_t)m0 * ND, Sl + (size_t)m0 * ND,
                    H + (size_t)n0 * ND, nullptr, ND, ND, ND / 64, acc);

    float* s_inv = (float*)smem;
    int t = threadIdx.x;
    if (t < 128) s_inv[t] = g_inv[b * ND + n0 + t];
    __syncthreads();

    int lane = t & 31, wid = t >> 5;
    int warp_m = (wid & 3) * 32, warp_n = (wid >> 2) * 64;
    int r4 = lane >> 2, c2 = (lane & 3) * 2;
#pragma unroll
    for (int f = 0; f < 2; f++)
#pragma unroll
        for (int h = 0; h < 2; h++) {
            int m = warp_m + f * 16 + r4 + h * 8;
            if (!FINAL) {
                uint32_t* rh = (uint32_t*)(g_Ehi + ((size_t)b * NC + m0 + m) * ND + n0);
                uint32_t* rl = (uint32_t*)(g_Elo + ((size_t)b * NC + m0 + m) * ND + n0);
#pragma unroll
                for (int nt = 0; nt < 8; nt++) {
                    int n = warp_n + nt * 8 + c2;
                    float v0 = acc[f][nt][2 * h] * s_inv[n];
                    float v1 = acc[f][nt][2 * h + 1] * s_inv[n + 1];
                    bf16 h0 = __float2bfloat16(v0), h1 = __float2bfloat16(v1);
                    bf16 l0 = __float2bfloat16(v0 - __bfloat162float(h0));
                    bf16 l1 = __float2bfloat16(v1 - __bfloat162float(h1));
                    rh[n >> 1] = pk2(h0, h1);
                    rl[n >> 1] = pk2(l0, l1);
                }
            } else {
                const float* xrow = xres + ((size_t)b * NC + m0 + m) * ND + n0;
                float* orow = out + ((size_t)b * NC + m0 + m) * ND + n0;
#pragma unroll
                for (int nt = 0; nt < 8; nt++) {
                    int n = warp_n + nt * 8 + c2;
                    float2 xv = *(const float2*)(xrow + n);
                    float2 o;
                    o.x = acc[f][nt][2 * h] * s_inv[n] + xv.x;
                    o.y = acc[f][nt][2 * h + 1] * s_inv[n + 1] + xv.y;
                    *(float2*)(orow + n) = o;
                }
            }
        }
}

// ---------------- prep / small kernels ----------------
__global__ void k_prep_xt(const float* __restrict__ x) {
    __shared__ float tile[32][33];
    int b = blockIdx.z;
    int d0 = blockIdx.x * 32, c0 = blockIdx.y * 32;
    const float* xb = x + (size_t)b * NC * ND;
    int tx = threadIdx.x, ty = threadIdx.y;  // 32x8
#pragma unroll
    for (int i = 0; i < 32; i += 8)
        tile[ty + i][tx] = xb[(size_t)(c0 + ty + i) * ND + d0 + tx];
    __syncthreads();
    bf16* oh = g_xthi + (size_t)b * ND * NC;
    bf16* ol = g_xtlo + (size_t)b * ND * NC;
#pragma unroll
    for (int i = 0; i < 32; i += 8) {
        float v = tile[tx][ty + i];
        bf16 h = __float2bfloat16(v);
        bf16 l = __float2bfloat16(v - __bfloat162float(h));
        size_t idx = (size_t)(d0 + ty + i) * NC + c0 + tx;
        oh[idx] = h;
        ol[idx] = l;
    }
}

__global__ void __launch_bounds__(256) k_sq(const float* __restrict__ x) {
    int gid = blockIdx.x * 256 + threadIdx.x;  // b*ND + d
    int b = gid >> 11, d = gid & (ND - 1);
    const float* xb = x + (size_t)b * NC * ND + d;
    float s = 0.f;
#pragma unroll 8
    for (int c = 0; c < NC; c++) {
        float v = xb[(size_t)c * ND];
        s += v * v;
    }
    g_sq[gid] = s;
}

__global__ void __launch_bounds__(256) k_prep_w(const float* __restrict__ W) {
    int i = blockIdx.x * 256 + threadIdx.x;
    float v = W[i];
    bf16 h = __float2bfloat16(v);
    g_whi[i] = h;
    g_wlo[i] = __float2bfloat16(v - __bfloat162float(h));
}

__global__ void __launch_bounds__(256) k_deg() {
    size_t row = blockIdx.x;
    const bf16* p = g_hg + row * ND;
    int t = threadIdx.x;
    uint4 v = *(const uint4*)(p + t * 8);
    float s = 0.f;
    uint32_t u[4] = {v.x, v.y, v.z, v.w};
#pragma unroll
    for (int i = 0; i < 4; i++) {
        float2 f = __bfloat1622float2(*(__nv_bfloat162*)&u[i]);
        s += f.x + f.y;
    }
    __shared__ float red[256];
    red[t] = s;
    __syncthreads();
    for (int o = 128; o > 0; o >>= 1) {
        if (t < o) red[t] += red[t + o];
        __syncthreads();
    }
    if (t == 0) g_inv[row] = (red[0] > 0.f) ? (1.f / red[0]) : 0.f;
}

__global__ void __launch_bounds__(256) k_ln(float* __restrict__ out,
                                            const float* __restrict__ gamma,
                                            const float* __restrict__ beta) {
    int row = blockIdx.x;  // b*NC + c
    float* p = out + (size_t)row * ND;
    int t = threadIdx.x;
    float4 v0 = *(float4*)(p + t * 8);
    float4 v1 = *(float4*)(p + t * 8 + 4);
    float vals[8] = {v0.x, v0.y, v0.z, v0.w, v1.x, v1.y, v1.z, v1.w};
    float s = 0.f, s2 = 0.f;
#pragma unroll
    for (int u = 0; u < 8; u++) {
        s += vals[u];
        s2 += vals[u] * vals[u];
    }
    __shared__ float r1[256];
    __shared__ float r2[256];
    r1[t] = s;
    r2[t] = s2;
    __syncthreads();
    for (int o = 128; o > 0; o >>= 1) {
        if (t < o) {
            r1[t] += r1[t + o];
            r2[t] += r2[t + o];
        }
        __syncthreads();
    }
    float mean = r1[0] * (1.f / ND);
    float var = r2[0] * (1.f / ND) - mean * mean;
    float rstd = rsqrtf(var + 1e-5f);
#pragma unroll
    for (int u = 0; u < 8; u++) {
        int d = t * 8 + u;
        float yn = (vals[u] - mean) * rstd * gamma[d] + beta[d];
        vals[u] = yn / (1.f + expf(-yn));
    }
    v0.x = vals[0]; v0.y = vals[1]; v0.z = vals[2]; v0.w = vals[3];
    v1.x = vals[4]; v1.y = vals[5]; v1.z = vals[6]; v1.w = vals[7];
    *(float4*)(p + t * 8) = v0;
    *(float4*)(p + t * 8 + 4) = v1;
}

// ---------------- launch ----------------
extern "C" void kernel_launch(void* const* d_in, const int* in_sizes, int n_in,
                              void* d_out, int out_size) {
    const float* x = (const float*)d_in[0];
    const float* W = (const float*)d_in[1];
    const float* bias = (const float*)d_in[2];
    const float* gamma = (const float*)d_in[3];
    const float* beta = (const float*)d_in[4];
    float* out = (float*)d_out;
    (void)in_sizes; (void)n_in; (void)out_size;

    const int SMEM_4 = 2 * 4 * 16384;  // 131072 (gram, fc)
    const int SMEM_3 = 2 * 3 * 16384;  // 98304  (agg)
    static bool attr_set = false;
    if (!attr_set) {
        cudaFuncSetAttribute(k_gram_mma, cudaFuncAttributeMaxDynamicSharedMemorySize, SMEM_4);
        cudaFuncSetAttribute(k_fc_mma, cudaFuncAttributeMaxDynamicSharedMemorySize, SMEM_4);
        cudaFuncSetAttribute(k_agg_mma<false>, cudaFuncAttributeMaxDynamicSharedMemorySize, SMEM_3);
        cudaFuncSetAttribute(k_agg_mma<true>, cudaFuncAttributeMaxDynamicSharedMemorySize, SMEM_3);
        attr_set = true;
    }

    k_prep_xt<<<dim3(ND / 32, NC / 32, NB), dim3(32, 8)>>>(x);
    k_sq<<<NB * ND / 256, 256>>>(x);
    k_prep_w<<<NC * NC / 256, 256>>>(W);
    k_fc_mma<<<dim3(ND / 128, NC / 128, NB), 256, SMEM_4>>>(bias);
    k_gram_mma<<<dim3(ND / 128, ND / 128, NB), 256, SMEM_4>>>();
    k_deg<<<NB * ND, 256>>>();
    k_agg_mma<false><<<dim3(ND / 128, NC / 128, NB), 256, SMEM_3>>>(nullptr, nullptr);
    k_agg_mma<true><<<dim3(ND / 128, NC / 128, NB), 256, SMEM_3>>>(x, out);
    k_ln<<<NB * NC, 256>>>(out, gamma, beta);
}

// round 6
// speedup vs baseline: 5.6544x; 1.5891x over previous
#include <cuda_runtime.h>
#include <cuda_bf16.h>
#include <cstdint>

#define NB 8
#define NC 256
#define ND 2048
typedef __nv_bfloat16 bf16;

// ---------------- static scratch ----------------
__device__ __align__(128) bf16  g_xthi[NB * ND * NC];
__device__ __align__(128) bf16  g_xtlo[NB * ND * NC];
__device__ __align__(128) float g_sq[NB * ND];
__device__ __align__(128) bf16  g_whi[NC * NC];
__device__ __align__(128) bf16  g_xfhi[NB * NC * ND];   // [b][o][d]
__device__ __align__(128) bf16  g_hg[(size_t)NB * ND * ND];
__device__ __align__(128) float g_inv[NB * ND];
__device__ __align__(128) bf16  g_Ehi[NB * NC * ND];    // [b][o][d]

// ---------------- helpers ----------------
__device__ __forceinline__ uint32_t smem_u32(const void* p) {
    uint32_t a;
    asm("{ .reg .u64 t; cvta.to.shared.u64 t, %1; cvt.u32.u64 %0, t; }" : "=r"(a) : "l"(p));
    return a;
}
#define SW128(x) ((x) ^ (((x) >> 3) & 0x70))

__device__ __forceinline__ void cp16(uint32_t dst, const void* src) {
    asm volatile("cp.async.cg.shared.global [%0], [%1], 16;\n" :: "r"(dst), "l"(src));
}
__device__ __forceinline__ void cpa_commit() { asm volatile("cp.async.commit_group;\n" ::: "memory"); }
template <int N>
__device__ __forceinline__ void cpa_waitN() { asm volatile("cp.async.wait_group %0;\n" :: "n"(N) : "memory"); }

__device__ __forceinline__ void ldm4(uint32_t* r, uint32_t addr) {
    asm volatile("ldmatrix.sync.aligned.m8n8.x4.shared.b16 {%0,%1,%2,%3}, [%4];"
                 : "=r"(r[0]), "=r"(r[1]), "=r"(r[2]), "=r"(r[3]) : "r"(addr));
}
__device__ __forceinline__ void mma16816(float* d, const uint32_t* a, const uint32_t* b) {
    asm volatile(
        "mma.sync.aligned.m16n8k16.row.col.f32.bf16.bf16.f32 "
        "{%0,%1,%2,%3}, {%4,%5,%6,%7}, {%8,%9}, {%0,%1,%2,%3};"
        : "+f"(d[0]), "+f"(d[1]), "+f"(d[2]), "+f"(d[3])
        : "r"(a[0]), "r"(a[1]), "r"(a[2]), "r"(a[3]), "r"(b[0]), "r"(b[1]));
}
__device__ __forceinline__ uint32_t pk2(bf16 a, bf16 b) {
    return (uint32_t)__bfloat16_as_ushort(a) | ((uint32_t)__bfloat16_as_ushort(b) << 16);
}

// load one 128-row x 64-col bf16 chunk into SW128 smem tile (256 threads)
__device__ __forceinline__ void load_tile256(uint32_t tb, const bf16* g, size_t rs, int kc, int t) {
#pragma unroll
    for (int i = 0; i < 4; i++) {
        int lin = i * 256 + t;
        int row = lin >> 3, seg = lin & 7;
        cp16(tb + SW128(row * 128 + seg * 16), g + (size_t)row * rs + kc + seg * 8);
    }
}

// ---------------- block GEMM mainloop ----------------
// 128x128 tile; A tiles {A0[,A1]}, B tiles {B0[,B1]}; combos: all (pa,pb) except (1,1).
template <int NA, int NBt, int NSTAGES>
__device__ __forceinline__ void gemm_main(
    uint32_t sb, const bf16* A0, const bf16* A1, const bf16* B0, const bf16* B1,
    size_t sA, size_t sB, int nchunks, float acc[2][8][4])
{
    const uint32_t TS = 16384u;
    const uint32_t STAGE = (NA + NBt) * TS;
    int t = threadIdx.x;
    int lane = t & 31, wid = t >> 5;
    int warp_m = (wid & 3) * 32, warp_n = (wid >> 2) * 64;
    int lrow = lane & 15;
    int lcol = (lane & 16) ? 16 : 0;

    // prologue: chunks 0..NSTAGES-2
#pragma unroll
    for (int s = 0; s < NSTAGES - 1; s++) {
        uint32_t st = sb + (uint32_t)s * STAGE;
        int kc = s * 64;
        load_tile256(st + 0 * TS, A0, sA, kc, t);
        if (NA == 2) load_tile256(st + 1 * TS, A1, sA, kc, t);
        load_tile256(st + NA * TS, B0, sB, kc, t);
        if (NBt == 2) load_tile256(st + (NA + 1) * TS, B1, sB, kc, t);
        cpa_commit();
    }
    for (int c = 0; c < nchunks; c++) {
        uint32_t cur = sb + (uint32_t)(c % NSTAGES) * STAGE;
        int cn = c + NSTAGES - 1;
        if (cn < nchunks) {
            uint32_t nx = sb + (uint32_t)(cn % NSTAGES) * STAGE;
            int kc = cn * 64;
            load_tile256(nx + 0 * TS, A0, sA, kc, t);
            if (NA == 2) load_tile256(nx + 1 * TS, A1, sA, kc, t);
            load_tile256(nx + NA * TS, B0, sB, kc, t);
            if (NBt == 2) load_tile256(nx + (NA + 1) * TS, B1, sB, kc, t);
        }
        cpa_commit();
        cpa_waitN<NSTAGES - 1>();
        __syncthreads();
#pragma unroll
        for (int ks = 0; ks < 4; ks++) {
            int kb = ks * 32 + lcol;
            uint32_t a[NA][2][4];
#pragma unroll
            for (int v = 0; v < NA; v++)
#pragma unroll
                for (int f = 0; f < 2; f++)
                    ldm4(a[v][f], cur + v * TS + SW128((warp_m + f * 16 + lrow) * 128 + kb));
            uint32_t bfr[NBt][8][2];
#pragma unroll
            for (int v = 0; v < NBt; v++)
#pragma unroll
                for (int np = 0; np < 4; np++) {
                    uint32_t r[4];
                    ldm4(r, cur + (NA + v) * TS + SW128((warp_n + np * 16 + lrow) * 128 + kb));
                    bfr[v][2 * np][0] = r[0]; bfr[v][2 * np][1] = r[2];
                    bfr[v][2 * np + 1][0] = r[1]; bfr[v][2 * np + 1][1] = r[3];
                }
#pragma unroll
            for (int pa = 0; pa < NA; pa++)
#pragma unroll
                for (int pb = 0; pb < NBt; pb++) {
                    if (pa == 1 && pb == 1) continue;
#pragma unroll
                    for (int f = 0; f < 2; f++)
#pragma unroll
                        for (int nt = 0; nt < 8; nt++)
                            mma16816(acc[f][nt], a[pa][f], bfr[pb][nt]);
                }
        }
        __syncthreads();
    }
}

// ---------------- GEMM kernels ----------------
// Gram + threshold: hg[m][n] = (sq_m + sq_n - 2*dot < 484); symmetric -> only j>=i blocks.
__global__ void __launch_bounds__(256) k_gram_mma() {
    int i = blockIdx.y, j = blockIdx.x;
    if (j < i) return;
    extern __shared__ char smem[];
    uint32_t sb = smem_u32(smem);
    int b = blockIdx.z, m0 = i * 128, n0 = j * 128;
    const bf16* Xh = g_xthi + (size_t)b * ND * NC;
    const bf16* Xl = g_xtlo + (size_t)b * ND * NC;
    float acc[2][8][4] = {};
    gemm_main<2, 2, 2>(sb, Xh + (size_t)m0 * NC, Xl + (size_t)m0 * NC,
                       Xh + (size_t)n0 * NC, Xl + (size_t)n0 * NC, NC, NC, NC / 64, acc);

    float* s_sqm = (float*)smem;
    float* s_sqn = s_sqm + 128;
    bf16* tr = (bf16*)(smem + 1024);  // [128][136] transpose staging
    int t = threadIdx.x;
    if (t < 128) s_sqm[t] = g_sq[b * ND + m0 + t];
    else s_sqn[t - 128] = g_sq[b * ND + n0 + (t - 128)];
    __syncthreads();

    int lane = t & 31, wid = t >> 5;
    int warp_m = (wid & 3) * 32, warp_n = (wid >> 2) * 64;
    int r4 = lane >> 2, c2 = (lane & 3) * 2;
    bf16* Hb = g_hg + (size_t)b * ND * ND;
    const bf16 one = __float2bfloat16(1.f), zero = __float2bfloat16(0.f);
    bool mirror = (j > i);
#pragma unroll
    for (int f = 0; f < 2; f++)
#pragma unroll
        for (int h = 0; h < 2; h++) {
            int m = warp_m + f * 16 + r4 + h * 8;
            float sm = s_sqm[m];
            uint32_t* hrow = (uint32_t*)(Hb + (size_t)(m0 + m) * ND + n0);
#pragma unroll
            for (int nt = 0; nt < 8; nt++) {
                int n = warp_n + nt * 8 + c2;
                float d0 = sm + s_sqn[n] - 2.f * acc[f][nt][2 * h];
                float d1 = sm + s_sqn[n + 1] - 2.f * acc[f][nt][2 * h + 1];
                bf16 v0 = d0 < 484.f ? one : zero;
                bf16 v1 = d1 < 484.f ? one : zero;
                hrow[n >> 1] = pk2(v0, v1);
                if (mirror) {
                    tr[(size_t)n * 136 + m] = v0;
                    tr[(size_t)(n + 1) * 136 + m] = v1;
                }
            }
        }
    if (mirror) {
        __syncthreads();
        int r = t >> 1, half = t & 1;
        uint4* dst = (uint4*)(Hb + (size_t)(n0 + r) * ND + m0 + half * 64);
        const uint4* src = (const uint4*)(tr + (size_t)r * 136 + half * 64);
#pragma unroll
        for (int k = 0; k < 8; k++) dst[k] = src[k];
    }
}

// FC: xf_T[o][d] = sum_c W[o][c]*xt[d][c] + bias[o]  (bf16-only)
__global__ void __launch_bounds__(256) k_fc_mma(const float* __restrict__ bias) {
    extern __shared__ char smem[];
    uint32_t sb = smem_u32(smem);
    int b = blockIdx.z, m0 = blockIdx.y * 128, n0 = blockIdx.x * 128;
    const bf16* Xh = g_xthi + (size_t)b * ND * NC;
    float acc[2][8][4] = {};
    gemm_main<1, 1, 4>(sb, g_whi + (size_t)m0 * NC, nullptr,
                       Xh + (size_t)n0 * NC, nullptr, NC, NC, NC / 64, acc);

    int t = threadIdx.x;
    int lane = t & 31, wid = t >> 5;
    int warp_m = (wid & 3) * 32, warp_n = (wid >> 2) * 64;
    int r4 = lane >> 2, c2 = (lane & 3) * 2;
#pragma unroll
    for (int f = 0; f < 2; f++)
#pragma unroll
        for (int h = 0; h < 2; h++) {
            int m = warp_m + f * 16 + r4 + h * 8;
            float bv = bias[m0 + m];
            uint32_t* rh = (uint32_t*)(g_xfhi + ((size_t)b * NC + m0 + m) * ND + n0);
#pragma unroll
            for (int nt = 0; nt < 8; nt++) {
                int n = warp_n + nt * 8 + c2;
                rh[n >> 1] = pk2(__float2bfloat16(acc[f][nt][2 * h] + bv),
                                 __float2bfloat16(acc[f][nt][2 * h + 1] + bv));
            }
        }
}

// AGG: D[o][n] = sum_k S[o][k]*hg[n][k]; scale by inv[n]; FINAL adds residual x.
template <bool FINAL>
__global__ void __launch_bounds__(256) k_agg_mma(const float* __restrict__ xres,
                                                 float* __restrict__ out) {
    extern __shared__ char smem[];
    uint32_t sb = smem_u32(smem);
    int b = blockIdx.z, m0 = blockIdx.y * 128, n0 = blockIdx.x * 128;
    const bf16* Sh = (FINAL ? g_Ehi : g_xfhi) + (size_t)b * NC * ND;
    const bf16* H = g_hg + (size_t)b * ND * ND;
    float acc[2][8][4] = {};
    gemm_main<1, 1, 4>(sb, Sh + (size_t)m0 * ND, nullptr,
                       H + (size_t)n0 * ND, nullptr, ND, ND, ND / 64, acc);

    float* s_inv = (float*)smem;
    int t = threadIdx.x;
    if (t < 128) s_inv[t] = g_inv[b * ND + n0 + t];
    __syncthreads();

    int lane = t & 31, wid = t >> 5;
    int warp_m = (wid & 3) * 32, warp_n = (wid >> 2) * 64;
    int r4 = lane >> 2, c2 = (lane & 3) * 2;
#pragma unroll
    for (int f = 0; f < 2; f++)
#pragma unroll
        for (int h = 0; h < 2; h++) {
            int m = warp_m + f * 16 + r4 + h * 8;
            if (!FINAL) {
                uint32_t* rh = (uint32_t*)(g_Ehi + ((size_t)b * NC + m0 + m) * ND + n0);
#pragma unroll
                for (int nt = 0; nt < 8; nt++) {
                    int n = warp_n + nt * 8 + c2;
                    rh[n >> 1] = pk2(__float2bfloat16(acc[f][nt][2 * h] * s_inv[n]),
                                     __float2bfloat16(acc[f][nt][2 * h + 1] * s_inv[n + 1]));
                }
            } else {
                const float* xrow = xres + ((size_t)b * NC + m0 + m) * ND + n0;
                float* orow = out + ((size_t)b * NC + m0 + m) * ND + n0;
#pragma unroll
                for (int nt = 0; nt < 8; nt++) {
                    int n = warp_n + nt * 8 + c2;
                    float2 xv = *(const float2*)(xrow + n);
                    float2 o;
                    o.x = acc[f][nt][2 * h] * s_inv[n] + xv.x;
                    o.y = acc[f][nt][2 * h + 1] * s_inv[n + 1] + xv.y;
                    *(float2*)(orow + n) = o;
                }
            }
        }
}

// ---------------- prep / small kernels ----------------
__global__ void k_prep_xt(const float* __restrict__ x) {
    __shared__ float tile[32][33];
    int b = blockIdx.z;
    int d0 = blockIdx.x * 32, c0 = blockIdx.y * 32;
    const float* xb = x + (size_t)b * NC * ND;
    int tx = threadIdx.x, ty = threadIdx.y;  // 32x8
#pragma unroll
    for (int i = 0; i < 32; i += 8)
        tile[ty + i][tx] = xb[(size_t)(c0 + ty + i) * ND + d0 + tx];
    __syncthreads();
    bf16* oh = g_xthi + (size_t)b * ND * NC;
    bf16* ol = g_xtlo + (size_t)b * ND * NC;
#pragma unroll
    for (int i = 0; i < 32; i += 8) {
        float v = tile[tx][ty + i];
        bf16 h = __float2bfloat16(v);
        bf16 l = __float2bfloat16(v - __bfloat162float(h));
        size_t idx = (size_t)(d0 + ty + i) * NC + c0 + tx;
        oh[idx] = h;
        ol[idx] = l;
    }
}

__global__ void __launch_bounds__(256) k_sq(const float* __restrict__ x) {
    int gid = blockIdx.x * 256 + threadIdx.x;  // b*ND + d
    int b = gid >> 11, d = gid & (ND - 1);
    const float* xb = x + (size_t)b * NC * ND + d;
    float s = 0.f;
#pragma unroll 8
    for (int c = 0; c < NC; c++) {
        float v = xb[(size_t)c * ND];
        s += v * v;
    }
    g_sq[gid] = s;
}

__global__ void __launch_bounds__(256) k_prep_w(const float* __restrict__ W) {
    int i = blockIdx.x * 256 + threadIdx.x;
    g_whi[i] = __float2bfloat16(W[i]);
}

__global__ void __launch_bounds__(256) k_deg() {
    size_t row = blockIdx.x;
    const bf16* p = g_hg + row * ND;
    int t = threadIdx.x;
    uint4 v = *(const uint4*)(p + t * 8);
    float s = 0.f;
    uint32_t u[4] = {v.x, v.y, v.z, v.w};
#pragma unroll
    for (int i = 0; i < 4; i++) {
        float2 f = __bfloat1622float2(*(__nv_bfloat162*)&u[i]);
        s += f.x + f.y;
    }
    __shared__ float red[256];
    red[t] = s;
    __syncthreads();
    for (int o = 128; o > 0; o >>= 1) {
        if (t < o) red[t] += red[t + o];
        __syncthreads();
    }
    if (t == 0) g_inv[row] = (red[0] > 0.f) ? (1.f / red[0]) : 0.f;
}

__global__ void __launch_bounds__(256) k_ln(float* __restrict__ out,
                                            const float* __restrict__ gamma,
                                            const float* __restrict__ beta) {
    int row = blockIdx.x;  // b*NC + c
    float* p = out + (size_t)row * ND;
    int t = threadIdx.x;
    float4 v0 = *(float4*)(p + t * 8);
    float4 v1 = *(float4*)(p + t * 8 + 4);
    float vals[8] = {v0.x, v0.y, v0.z, v0.w, v1.x, v1.y, v1.z, v1.w};
    float s = 0.f, s2 = 0.f;
#pragma unroll
    for (int u = 0; u < 8; u++) {
        s += vals[u];
        s2 += vals[u] * vals[u];
    }
    __shared__ float r1[256];
    __shared__ float r2[256];
    r1[t] = s;
    r2[t] = s2;
    __syncthreads();
    for (int o = 128; o > 0; o >>= 1) {
        if (t < o) {
            r1[t] += r1[t + o];
            r2[t] += r2[t + o];
        }
        __syncthreads();
    }
    float mean = r1[0] * (1.f / ND);
    float var = r2[0] * (1.f / ND) - mean * mean;
    float rstd = rsqrtf(var + 1e-5f);
#pragma unroll
    for (int u = 0; u < 8; u++) {
        int d = t * 8 + u;
        float yn = (vals[u] - mean) * rstd * gamma[d] + beta[d];
        vals[u] = yn / (1.f + expf(-yn));
    }
    v0.x = vals[0]; v0.y = vals[1]; v0.z = vals[2]; v0.w = vals[3];
    v1.x = vals[4]; v1.y = vals[5]; v1.z = vals[6]; v1.w = vals[7];
    *(float4*)(p + t * 8) = v0;
    *(float4*)(p + t * 8 + 4) = v1;
}

// ---------------- launch ----------------
extern "C" void kernel_launch(void* const* d_in, const int* in_sizes, int n_in,
                              void* d_out, int out_size) {
    const float* x = (const float*)d_in[0];
    const float* W = (const float*)d_in[1];
    const float* bias = (const float*)d_in[2];
    const float* gamma = (const float*)d_in[3];
    const float* beta = (const float*)d_in[4];
    float* out = (float*)d_out;
    (void)in_sizes; (void)n_in; (void)out_size;

    const int SMEM_BIG = 2 * 4 * 16384;  // 131072 bytes (all GEMM kernels)
    static bool attr_set = false;
    if (!attr_set) {
        cudaFuncSetAttribute(k_gram_mma, cudaFuncAttributeMaxDynamicSharedMemorySize, SMEM_BIG);
        cudaFuncSetAttribute(k_fc_mma, cudaFuncAttributeMaxDynamicSharedMemorySize, SMEM_BIG);
        cudaFuncSetAttribute(k_agg_mma<false>, cudaFuncAttributeMaxDynamicSharedMemorySize, SMEM_BIG);
        cudaFuncSetAttribute(k_agg_mma<true>, cudaFuncAttributeMaxDynamicSharedMemorySize, SMEM_BIG);
        attr_set = true;
    }

    k_prep_xt<<<dim3(ND / 32, NC / 32, NB), dim3(32, 8)>>>(x);
    k_sq<<<NB * ND / 256, 256>>>(x);
    k_prep_w<<<NC * NC / 256, 256>>>(W);
    k_fc_mma<<<dim3(ND / 128, NC / 128, NB), 256, SMEM_BIG>>>(bias);
    k_gram_mma<<<dim3(ND / 128, ND / 128, NB), 256, SMEM_BIG>>>();
    k_deg<<<NB * ND, 256>>>();
    k_agg_mma<false><<<dim3(ND / 128, NC / 128, NB), 256, SMEM_BIG>>>(nullptr, nullptr);
    k_agg_mma<true><<<dim3(ND / 128, NC / 128, NB), 256, SMEM_BIG>>>(x, out);
    k_ln<<<NB * NC, 256>>>(out, gamma, beta);
}

// round 7
// speedup vs baseline: 5.6550x; 1.0001x over previous
#include <cuda_runtime.h>
#include <cuda_bf16.h>
#include <cstdint>

#define NB 8
#define NC 256
#define ND 2048
typedef __nv_bfloat16 bf16;

// ---------------- static scratch ----------------
__device__ __align__(128) bf16  g_xthi[NB * ND * NC];
__device__ __align__(128) bf16  g_xtlo[NB * ND * NC];
__device__ __align__(128) float g_sq[NB * ND];
__device__ __align__(128) bf16  g_whi[NC * NC];
__device__ __align__(128) bf16  g_xfhi[NB * NC * ND];   // [b][o][d]
__device__ __align__(128) bf16  g_hg[(size_t)NB * ND * ND];
__device__ __align__(128) float g_inv[NB * ND];
__device__ __align__(128) bf16  g_Ehi[NB * NC * ND];    // [b][o][d]

// ---------------- helpers ----------------
__device__ __forceinline__ uint32_t smem_u32(const void* p) {
    uint32_t a;
    asm("{ .reg .u64 t; cvta.to.shared.u64 t, %1; cvt.u32.u64 %0, t; }" : "=r"(a) : "l"(p));
    return a;
}
#define SW128(x) ((x) ^ (((x) >> 3) & 0x70))

__device__ __forceinline__ void cp16(uint32_t dst, const void* src) {
    asm volatile("cp.async.cg.shared.global [%0], [%1], 16;\n" :: "r"(dst), "l"(src));
}
__device__ __forceinline__ void cpa_commit() { asm volatile("cp.async.commit_group;\n" ::: "memory"); }
template <int N>
__device__ __forceinline__ void cpa_waitN() { asm volatile("cp.async.wait_group %0;\n" :: "n"(N) : "memory"); }

__device__ __forceinline__ void ldm4(uint32_t* r, uint32_t addr) {
    asm volatile("ldmatrix.sync.aligned.m8n8.x4.shared.b16 {%0,%1,%2,%3}, [%4];"
                 : "=r"(r[0]), "=r"(r[1]), "=r"(r[2]), "=r"(r[3]) : "r"(addr));
}
__device__ __forceinline__ void mma16816(float* d, const uint32_t* a, const uint32_t* b) {
    asm volatile(
        "mma.sync.aligned.m16n8k16.row.col.f32.bf16.bf16.f32 "
        "{%0,%1,%2,%3}, {%4,%5,%6,%7}, {%8,%9}, {%0,%1,%2,%3};"
        : "+f"(d[0]), "+f"(d[1]), "+f"(d[2]), "+f"(d[3])
        : "r"(a[0]), "r"(a[1]), "r"(a[2]), "r"(a[3]), "r"(b[0]), "r"(b[1]));
}
__device__ __forceinline__ uint32_t pk2(bf16 a, bf16 b) {
    return (uint32_t)__bfloat16_as_ushort(a) | ((uint32_t)__bfloat16_as_ushort(b) << 16);
}

// load one 128-row x 64-col bf16 chunk into SW128 smem tile (256 threads)
__device__ __forceinline__ void load_tile256(uint32_t tb, const bf16* g, size_t rs, int kc, int t) {
#pragma unroll
    for (int i = 0; i < 4; i++) {
        int lin = i * 256 + t;
        int row = lin >> 3, seg = lin & 7;
        cp16(tb + SW128(row * 128 + seg * 16), g + (size_t)row * rs + kc + seg * 8);
    }
}

// ---------------- block GEMM mainloop ----------------
// 128x128 tile; A tiles {A0[,A1]}, B tiles {B0[,B1]}; combos: all (pa,pb) except (1,1).
template <int NA, int NBt, int NSTAGES>
__device__ __forceinline__ void gemm_main(
    uint32_t sb, const bf16* A0, const bf16* A1, const bf16* B0, const bf16* B1,
    size_t sA, size_t sB, int nchunks, float acc[2][8][4])
{
    const uint32_t TS = 16384u;
    const uint32_t STAGE = (NA + NBt) * TS;
    int t = threadIdx.x;
    int lane = t & 31, wid = t >> 5;
    int warp_m = (wid & 3) * 32, warp_n = (wid >> 2) * 64;
    int lrow = lane & 15;
    int lcol = (lane & 16) ? 16 : 0;

    // prologue: chunks 0..NSTAGES-2
#pragma unroll
    for (int s = 0; s < NSTAGES - 1; s++) {
        uint32_t st = sb + (uint32_t)s * STAGE;
        int kc = s * 64;
        load_tile256(st + 0 * TS, A0, sA, kc, t);
        if (NA == 2) load_tile256(st + 1 * TS, A1, sA, kc, t);
        load_tile256(st + NA * TS, B0, sB, kc, t);
        if (NBt == 2) load_tile256(st + (NA + 1) * TS, B1, sB, kc, t);
        cpa_commit();
    }
    for (int c = 0; c < nchunks; c++) {
        uint32_t cur = sb + (uint32_t)(c % NSTAGES) * STAGE;
        int cn = c + NSTAGES - 1;
        if (cn < nchunks) {
            uint32_t nx = sb + (uint32_t)(cn % NSTAGES) * STAGE;
            int kc = cn * 64;
            load_tile256(nx + 0 * TS, A0, sA, kc, t);
            if (NA == 2) load_tile256(nx + 1 * TS, A1, sA, kc, t);
            load_tile256(nx + NA * TS, B0, sB, kc, t);
            if (NBt == 2) load_tile256(nx + (NA + 1) * TS, B1, sB, kc, t);
        }
        cpa_commit();
        cpa_waitN<NSTAGES - 1>();
        __syncthreads();
#pragma unroll
        for (int ks = 0; ks < 4; ks++) {
            int kb = ks * 32 + lcol;
            uint32_t a[NA][2][4];
#pragma unroll
            for (int v = 0; v < NA; v++)
#pragma unroll
                for (int f = 0; f < 2; f++)
                    ldm4(a[v][f], cur + v * TS + SW128((warp_m + f * 16 + lrow) * 128 + kb));
            uint32_t bfr[NBt][8][2];
#pragma unroll
            for (int v = 0; v < NBt; v++)
#pragma unroll
                for (int np = 0; np < 4; np++) {
                    uint32_t r[4];
                    ldm4(r, cur + (NA + v) * TS + SW128((warp_n + np * 16 + lrow) * 128 + kb));
                    bfr[v][2 * np][0] = r[0]; bfr[v][2 * np][1] = r[2];
                    bfr[v][2 * np + 1][0] = r[1]; bfr[v][2 * np + 1][1] = r[3];
                }
#pragma unroll
            for (int pa = 0; pa < NA; pa++)
#pragma unroll
                for (int pb = 0; pb < NBt; pb++) {
                    if (pa == 1 && pb == 1) continue;
#pragma unroll
                    for (int f = 0; f < 2; f++)
#pragma unroll
                        for (int nt = 0; nt < 8; nt++)
                            mma16816(acc[f][nt], a[pa][f], bfr[pb][nt]);
                }
        }
        __syncthreads();
    }
}

// ---------------- GEMM kernels ----------------
// Gram + threshold: hg[m][n] = (sq_m + sq_n - 2*dot < 484); symmetric -> only j>=i blocks.
__global__ void __launch_bounds__(256) k_gram_mma() {
    int i = blockIdx.y, j = blockIdx.x;
    if (j < i) return;
    extern __shared__ char smem[];
    uint32_t sb = smem_u32(smem);
    int b = blockIdx.z, m0 = i * 128, n0 = j * 128;
    const bf16* Xh = g_xthi + (size_t)b * ND * NC;
    const bf16* Xl = g_xtlo + (size_t)b * ND * NC;
    float acc[2][8][4] = {};
    gemm_main<2, 2, 2>(sb, Xh + (size_t)m0 * NC, Xl + (size_t)m0 * NC,
                       Xh + (size_t)n0 * NC, Xl + (size_t)n0 * NC, NC, NC, NC / 64, acc);

    float* s_sqm = (float*)smem;
    float* s_sqn = s_sqm + 128;
    bf16* tr = (bf16*)(smem + 1024);  // [128][136] transpose staging
    int t = threadIdx.x;
    if (t < 128) s_sqm[t] = g_sq[b * ND + m0 + t];
    else s_sqn[t - 128] = g_sq[b * ND + n0 + (t - 128)];
    __syncthreads();

    int lane = t & 31, wid = t >> 5;
    int warp_m = (wid & 3) * 32, warp_n = (wid >> 2) * 64;
    int r4 = lane >> 2, c2 = (lane & 3) * 2;
    bf16* Hb = g_hg + (size_t)b * ND * ND;
    const bf16 one = __float2bfloat16(1.f), zero = __float2bfloat16(0.f);
    bool mirror = (j > i);
#pragma unroll
    for (int f = 0; f < 2; f++)
#pragma unroll
        for (int h = 0; h < 2; h++) {
            int m = warp_m + f * 16 + r4 + h * 8;
            float sm = s_sqm[m];
            uint32_t* hrow = (uint32_t*)(Hb + (size_t)(m0 + m) * ND + n0);
#pragma unroll
            for (int nt = 0; nt < 8; nt++) {
                int n = warp_n + nt * 8 + c2;
                float d0 = sm + s_sqn[n] - 2.f * acc[f][nt][2 * h];
                float d1 = sm + s_sqn[n + 1] - 2.f * acc[f][nt][2 * h + 1];
                bf16 v0 = d0 < 484.f ? one : zero;
                bf16 v1 = d1 < 484.f ? one : zero;
                hrow[n >> 1] = pk2(v0, v1);
                if (mirror) {
                    tr[(size_t)n * 136 + m] = v0;
                    tr[(size_t)(n + 1) * 136 + m] = v1;
                }
            }
        }
    if (mirror) {
        __syncthreads();
        int r = t >> 1, half = t & 1;
        uint4* dst = (uint4*)(Hb + (size_t)(n0 + r) * ND + m0 + half * 64);
        const uint4* src = (const uint4*)(tr + (size_t)r * 136 + half * 64);
#pragma unroll
        for (int k = 0; k < 8; k++) dst[k] = src[k];
    }
}

// FC: xf_T[o][d] = sum_c W[o][c]*xt[d][c] + bias[o]  (bf16-only)
__global__ void __launch_bounds__(256) k_fc_mma(const float* __restrict__ bias) {
    extern __shared__ char smem[];
    uint32_t sb = smem_u32(smem);
    int b = blockIdx.z, m0 = blockIdx.y * 128, n0 = blockIdx.x * 128;
    const bf16* Xh = g_xthi + (size_t)b * ND * NC;
    float acc[2][8][4] = {};
    gemm_main<1, 1, 4>(sb, g_whi + (size_t)m0 * NC, nullptr,
                       Xh + (size_t)n0 * NC, nullptr, NC, NC, NC / 64, acc);

    int t = threadIdx.x;
    int lane = t & 31, wid = t >> 5;
    int warp_m = (wid & 3) * 32, warp_n = (wid >> 2) * 64;
    int r4 = lane >> 2, c2 = (lane & 3) * 2;
#pragma unroll
    for (int f = 0; f < 2; f++)
#pragma unroll
        for (int h = 0; h < 2; h++) {
            int m = warp_m + f * 16 + r4 + h * 8;
            float bv = bias[m0 + m];
            uint32_t* rh = (uint32_t*)(g_xfhi + ((size_t)b * NC + m0 + m) * ND + n0);
#pragma unroll
            for (int nt = 0; nt < 8; nt++) {
                int n = warp_n + nt * 8 + c2;
                rh[n >> 1] = pk2(__float2bfloat16(acc[f][nt][2 * h] + bv),
                                 __float2bfloat16(acc[f][nt][2 * h + 1] + bv));
            }
        }
}

// AGG: D[o][n] = sum_k S[o][k]*hg[n][k]; scale by inv[n]; FINAL adds residual x.
template <bool FINAL>
__global__ void __launch_bounds__(256) k_agg_mma(const float* __restrict__ xres,
                                                 float* __restrict__ out) {
    extern __shared__ char smem[];
    uint32_t sb = smem_u32(smem);
    int b = blockIdx.z, m0 = blockIdx.y * 128, n0 = blockIdx.x * 128;
    const bf16* Sh = (FINAL ? g_Ehi : g_xfhi) + (size_t)b * NC * ND;
    const bf16* H = g_hg + (size_t)b * ND * ND;
    float acc[2][8][4] = {};
    gemm_main<1, 1, 4>(sb, Sh + (size_t)m0 * ND, nullptr,
                       H + (size_t)n0 * ND, nullptr, ND, ND, ND / 64, acc);

    float* s_inv = (float*)smem;
    int t = threadIdx.x;
    if (t < 128) s_inv[t] = g_inv[b * ND + n0 + t];
    __syncthreads();

    int lane = t & 31, wid = t >> 5;
    int warp_m = (wid & 3) * 32, warp_n = (wid >> 2) * 64;
    int r4 = lane >> 2, c2 = (lane & 3) * 2;
#pragma unroll
    for (int f = 0; f < 2; f++)
#pragma unroll
        for (int h = 0; h < 2; h++) {
            int m = warp_m + f * 16 + r4 + h * 8;
            if (!FINAL) {
                uint32_t* rh = (uint32_t*)(g_Ehi + ((size_t)b * NC + m0 + m) * ND + n0);
#pragma unroll
                for (int nt = 0; nt < 8; nt++) {
                    int n = warp_n + nt * 8 + c2;
                    rh[n >> 1] = pk2(__float2bfloat16(acc[f][nt][2 * h] * s_inv[n]),
                                     __float2bfloat16(acc[f][nt][2 * h + 1] * s_inv[n + 1]));
                }
            } else {
                const float* xrow = xres + ((size_t)b * NC + m0 + m) * ND + n0;
                float* orow = out + ((size_t)b * NC + m0 + m) * ND + n0;
#pragma unroll
                for (int nt = 0; nt < 8; nt++) {
                    int n = warp_n + nt * 8 + c2;
                    float2 xv = *(const float2*)(xrow + n);
                    float2 o;
                    o.x = acc[f][nt][2 * h] * s_inv[n] + xv.x;
                    o.y = acc[f][nt][2 * h + 1] * s_inv[n + 1] + xv.y;
                    *(float2*)(orow + n) = o;
                }
            }
        }
}

// ---------------- prep / small kernels ----------------
__global__ void k_prep_xt(const float* __restrict__ x) {
    __shared__ float tile[32][33];
    int b = blockIdx.z;
    int d0 = blockIdx.x * 32, c0 = blockIdx.y * 32;
    const float* xb = x + (size_t)b * NC * ND;
    int tx = threadIdx.x, ty = threadIdx.y;  // 32x8
#pragma unroll
    for (int i = 0; i < 32; i += 8)
        tile[ty + i][tx] = xb[(size_t)(c0 + ty + i) * ND + d0 + tx];
    __syncthreads();
    bf16* oh = g_xthi + (size_t)b * ND * NC;
    bf16* ol = g_xtlo + (size_t)b * ND * NC;
#pragma unroll
    for (int i = 0; i < 32; i += 8) {
        float v = tile[tx][ty + i];
        bf16 h = __float2bfloat16(v);
        bf16 l = __float2bfloat16(v - __bfloat162float(h));
        size_t idx = (size_t)(d0 + ty + i) * NC + c0 + tx;
        oh[idx] = h;
        ol[idx] = l;
    }
}

__global__ void __launch_bounds__(256) k_sq(const float* __restrict__ x) {
    int gid = blockIdx.x * 256 + threadIdx.x;  // b*ND + d
    int b = gid >> 11, d = gid & (ND - 1);
    const float* xb = x + (size_t)b * NC * ND + d;
    float s = 0.f;
#pragma unroll 8
    for (int c = 0; c < NC; c++) {
        float v = xb[(size_t)c * ND];
        s += v * v;
    }
    g_sq[gid] = s;
}

__global__ void __launch_bounds__(256) k_prep_w(const float* __restrict__ W) {
    int i = blockIdx.x * 256 + threadIdx.x;
    g_whi[i] = __float2bfloat16(W[i]);
}

__global__ void __launch_bounds__(256) k_deg() {
    size_t row = blockIdx.x;
    const bf16* p = g_hg + row * ND;
    int t = threadIdx.x;
    uint4 v = *(const uint4*)(p + t * 8);
    float s = 0.f;
    uint32_t u[4] = {v.x, v.y, v.z, v.w};
#pragma unroll
    for (int i = 0; i < 4; i++) {
        float2 f = __bfloat1622float2(*(__nv_bfloat162*)&u[i]);
        s += f.x + f.y;
    }
    __shared__ float red[256];
    red[t] = s;
    __syncthreads();
    for (int o = 128; o > 0; o >>= 1) {
        if (t < o) red[t] += red[t + o];
        __syncthreads();
    }
    if (t == 0) g_inv[row] = (red[0] > 0.f) ? (1.f / red[0]) : 0.f;
}

__global__ void __launch_bounds__(256) k_ln(float* __restrict__ out,
                                            const float* __restrict__ gamma,
                                            const float* __restrict__ beta) {
    int row = blockIdx.x;  // b*NC + c
    float* p = out + (size_t)row * ND;
    int t = threadIdx.x;
    float4 v0 = *(float4*)(p + t * 8);
    float4 v1 = *(float4*)(p + t * 8 + 4);
    float vals[8] = {v0.x, v0.y, v0.z, v0.w, v1.x, v1.y, v1.z, v1.w};
    float s = 0.f, s2 = 0.f;
#pragma unroll
    for (int u = 0; u < 8; u++) {
        s += vals[u];
        s2 += vals[u] * vals[u];
    }
    __shared__ float r1[256];
    __shared__ float r2[256];
    r1[t] = s;
    r2[t] = s2;
    __syncthreads();
    for (int o = 128; o > 0; o >>= 1) {
        if (t < o) {
            r1[t] += r1[t + o];
            r2[t] += r2[t + o];
        }
        __syncthreads();
    }
    float mean = r1[0] * (1.f / ND);
    float var = r2[0] * (1.f / ND) - mean * mean;
    float rstd = rsqrtf(var + 1e-5f);
#pragma unroll
    for (int u = 0; u < 8; u++) {
        int d = t * 8 + u;
        float yn = (vals[u] - mean) * rstd * gamma[d] + beta[d];
        vals[u] = yn / (1.f + expf(-yn));
    }
    v0.x = vals[0]; v0.y = vals[1]; v0.z = vals[2]; v0.w = vals[3];
    v1.x = vals[4]; v1.y = vals[5]; v1.z = vals[6]; v1.w = vals[7];
    *(float4*)(p + t * 8) = v0;
    *(float4*)(p + t * 8 + 4) = v1;
}

// ---------------- launch ----------------
extern "C" void kernel_launch(void* const* d_in, const int* in_sizes, int n_in,
                              void* d_out, int out_size) {
    const float* x = (const float*)d_in[0];
    const float* W = (const float*)d_in[1];
    const float* bias = (const float*)d_in[2];
    const float* gamma = (const float*)d_in[3];
    const float* beta = (const float*)d_in[4];
    float* out = (float*)d_out;
    (void)in_sizes; (void)n_in; (void)out_size;

    const int SMEM_BIG = 2 * 4 * 16384;  // 131072 bytes (all GEMM kernels)
    static bool attr_set = false;
    if (!attr_set) {
        cudaFuncSetAttribute(k_gram_mma, cudaFuncAttributeMaxDynamicSharedMemorySize, SMEM_BIG);
        cudaFuncSetAttribute(k_fc_mma, cudaFuncAttributeMaxDynamicSharedMemorySize, SMEM_BIG);
        cudaFuncSetAttribute(k_agg_mma<false>, cudaFuncAttributeMaxDynamicSharedMemorySize, SMEM_BIG);
        cudaFuncSetAttribute(k_agg_mma<true>, cudaFuncAttributeMaxDynamicSharedMemorySize, SMEM_BIG);
        attr_set = true;
    }

    k_prep_xt<<<dim3(ND / 32, NC / 32, NB), dim3(32, 8)>>>(x);
    k_sq<<<NB * ND / 256, 256>>>(x);
    k_prep_w<<<NC * NC / 256, 256>>>(W);
    k_fc_mma<<<dim3(ND / 128, NC / 128, NB), 256, SMEM_BIG>>>(bias);
    k_gram_mma<<<dim3(ND / 128, ND / 128, NB), 256, SMEM_BIG>>>();
    k_deg<<<NB * ND, 256>>>();
    k_agg_mma<false><<<dim3(ND / 128, NC / 128, NB), 256, SMEM_BIG>>>(nullptr, nullptr);
    k_agg_mma<true><<<dim3(ND / 128, NC / 128, NB), 256, SMEM_BIG>>>(x, out);
    k_ln<<<NB * NC, 256>>>(out, gamma, beta);
}

// round 8
// speedup vs baseline: 6.2690x; 1.1086x over previous
#include <cuda_runtime.h>
#include <cuda_bf16.h>
#include <cstdint>

#define NB 8
#define NC 256
#define ND 2048
typedef __nv_bfloat16 bf16;

// ---------------- static scratch ----------------
__device__ __align__(128) bf16  g_xthi[NB * ND * NC];
__device__ __align__(128) bf16  g_xtlo[NB * ND * NC];
__device__ __align__(128) float g_sq[NB * ND];
__device__ __align__(128) bf16  g_whi[NC * NC];
__device__ __align__(128) bf16  g_xfhi[NB * NC * ND];   // [b][o][d]
__device__ __align__(128) bf16  g_hg[(size_t)NB * ND * ND];
__device__ __align__(128) float g_deg[NB * ND];
__device__ __align__(128) float g_inv[NB * ND];
__device__ __align__(128) bf16  g_Ehi[NB * NC * ND];    // [b][o][d]

// ---------------- helpers ----------------
__device__ __forceinline__ uint32_t smem_u32(const void* p) {
    uint32_t a;
    asm("{ .reg .u64 t; cvta.to.shared.u64 t, %1; cvt.u32.u64 %0, t; }" : "=r"(a) : "l"(p));
    return a;
}
#define SW128(x) ((x) ^ (((x) >> 3) & 0x70))

__device__ __forceinline__ void cp16(uint32_t dst, const void* src) {
    asm volatile("cp.async.cg.shared.global [%0], [%1], 16;\n" :: "r"(dst), "l"(src));
}
__device__ __forceinline__ void cpa_commit() { asm volatile("cp.async.commit_group;\n" ::: "memory"); }
template <int N>
__device__ __forceinline__ void cpa_waitN() { asm volatile("cp.async.wait_group %0;\n" :: "n"(N) : "memory"); }

__device__ __forceinline__ void ldm4(uint32_t* r, uint32_t addr) {
    asm volatile("ldmatrix.sync.aligned.m8n8.x4.shared.b16 {%0,%1,%2,%3}, [%4];"
                 : "=r"(r[0]), "=r"(r[1]), "=r"(r[2]), "=r"(r[3]) : "r"(addr));
}
__device__ __forceinline__ void mma16816(float* d, const uint32_t* a, const uint32_t* b) {
    asm volatile(
        "mma.sync.aligned.m16n8k16.row.col.f32.bf16.bf16.f32 "
        "{%0,%1,%2,%3}, {%4,%5,%6,%7}, {%8,%9}, {%0,%1,%2,%3};"
        : "+f"(d[0]), "+f"(d[1]), "+f"(d[2]), "+f"(d[3])
        : "r"(a[0]), "r"(a[1]), "r"(a[2]), "r"(a[3]), "r"(b[0]), "r"(b[1]));
}
__device__ __forceinline__ uint32_t pk2(bf16 a, bf16 b) {
    return (uint32_t)__bfloat16_as_ushort(a) | ((uint32_t)__bfloat16_as_ushort(b) << 16);
}

// load one 128-row x 64-col bf16 chunk into SW128 smem tile (256 threads)
__device__ __forceinline__ void load_tile256(uint32_t tb, const bf16* g, size_t rs, int kc, int t) {
#pragma unroll
    for (int i = 0; i < 4; i++) {
        int lin = i * 256 + t;
        int row = lin >> 3, seg = lin & 7;
        cp16(tb + SW128(row * 128 + seg * 16), g + (size_t)row * rs + kc + seg * 8);
    }
}

// ---------------- block GEMM mainloop ----------------
template <int NA, int NBt, int NSTAGES>
__device__ __forceinline__ void gemm_main(
    uint32_t sb, const bf16* A0, const bf16* A1, const bf16* B0, const bf16* B1,
    size_t sA, size_t sB, int nchunks, float acc[2][8][4])
{
    const uint32_t TS = 16384u;
    const uint32_t STAGE = (NA + NBt) * TS;
    int t = threadIdx.x;
    int lane = t & 31, wid = t >> 5;
    int warp_m = (wid & 3) * 32, warp_n = (wid >> 2) * 64;
    int lrow = lane & 15;
    int lcol = (lane & 16) ? 16 : 0;

#pragma unroll
    for (int s = 0; s < NSTAGES - 1; s++) {
        uint32_t st = sb + (uint32_t)s * STAGE;
        int kc = s * 64;
        load_tile256(st + 0 * TS, A0, sA, kc, t);
        if (NA == 2) load_tile256(st + 1 * TS, A1, sA, kc, t);
        load_tile256(st + NA * TS, B0, sB, kc, t);
        if (NBt == 2) load_tile256(st + (NA + 1) * TS, B1, sB, kc, t);
        cpa_commit();
    }
    for (int c = 0; c < nchunks; c++) {
        uint32_t cur = sb + (uint32_t)(c % NSTAGES) * STAGE;
        int cn = c + NSTAGES - 1;
        if (cn < nchunks) {
            uint32_t nx = sb + (uint32_t)(cn % NSTAGES) * STAGE;
            int kc = cn * 64;
            load_tile256(nx + 0 * TS, A0, sA, kc, t);
            if (NA == 2) load_tile256(nx + 1 * TS, A1, sA, kc, t);
            load_tile256(nx + NA * TS, B0, sB, kc, t);
            if (NBt == 2) load_tile256(nx + (NA + 1) * TS, B1, sB, kc, t);
        }
        cpa_commit();
        cpa_waitN<NSTAGES - 1>();
        __syncthreads();
#pragma unroll
        for (int ks = 0; ks < 4; ks++) {
            int kb = ks * 32 + lcol;
            uint32_t a[NA][2][4];
#pragma unroll
            for (int v = 0; v < NA; v++)
#pragma unroll
                for (int f = 0; f < 2; f++)
                    ldm4(a[v][f], cur + v * TS + SW128((warp_m + f * 16 + lrow) * 128 + kb));
            uint32_t bfr[NBt][8][2];
#pragma unroll
            for (int v = 0; v < NBt; v++)
#pragma unroll
                for (int np = 0; np < 4; np++) {
                    uint32_t r[4];
                    ldm4(r, cur + (NA + v) * TS + SW128((warp_n + np * 16 + lrow) * 128 + kb));
                    bfr[v][2 * np][0] = r[0]; bfr[v][2 * np][1] = r[2];
                    bfr[v][2 * np + 1][0] = r[1]; bfr[v][2 * np + 1][1] = r[3];
                }
#pragma unroll
            for (int pa = 0; pa < NA; pa++)
#pragma unroll
                for (int pb = 0; pb < NBt; pb++) {
                    if (pa == 1 && pb == 1) continue;
#pragma unroll
                    for (int f = 0; f < 2; f++)
#pragma unroll
                        for (int nt = 0; nt < 8; nt++)
                            mma16816(acc[f][nt], a[pa][f], bfr[pb][nt]);
                }
        }
        __syncthreads();
    }
}

// ---------------- GEMM kernels ----------------
// Gram + threshold + fused degree. Triangular grid: blockIdx.x in [0,136).
__global__ void __launch_bounds__(256) k_gram_mma() {
    int L = blockIdx.x;
    int i = 0, rem = L;
    while (rem >= (ND / 128) - i) { rem -= (ND / 128) - i; i++; }
    int j = i + rem;

    extern __shared__ char smem[];
    uint32_t sb = smem_u32(smem);
    int b = blockIdx.z, m0 = i * 128, n0 = j * 128;
    const bf16* Xh = g_xthi + (size_t)b * ND * NC;
    const bf16* Xl = g_xtlo + (size_t)b * ND * NC;
    float acc[2][8][4] = {};
    gemm_main<2, 2, 3>(sb, Xh + (size_t)m0 * NC, Xl + (size_t)m0 * NC,
                       Xh + (size_t)n0 * NC, Xl + (size_t)n0 * NC, NC, NC, NC / 64, acc);

    float* s_sqm = (float*)smem;
    float* s_sqn = s_sqm + 128;
    bf16* tr = (bf16*)(smem + 1024);  // [128][136] transpose staging
    int t = threadIdx.x;
    if (t < 128) s_sqm[t] = g_sq[b * ND + m0 + t];
    else s_sqn[t - 128] = g_sq[b * ND + n0 + (t - 128)];
    __syncthreads();

    int lane = t & 31, wid = t >> 5;
    int warp_m = (wid & 3) * 32, warp_n = (wid >> 2) * 64;
    int r4 = lane >> 2, c2 = (lane & 3) * 2;
    bf16* Hb = g_hg + (size_t)b * ND * ND;
    float* degb = g_deg + b * ND;
    const bf16 one = __float2bfloat16(1.f), zero = __float2bfloat16(0.f);
    bool mirror = (j > i);
#pragma unroll
    for (int f = 0; f < 2; f++)
#pragma unroll
        for (int h = 0; h < 2; h++) {
            int m = warp_m + f * 16 + r4 + h * 8;
            float sm = s_sqm[m];
            uint32_t* hrow = (uint32_t*)(Hb + (size_t)(m0 + m) * ND + n0);
            float cnt = 0.f;
#pragma unroll
            for (int nt = 0; nt < 8; nt++) {
                int n = warp_n + nt * 8 + c2;
                float d0 = sm + s_sqn[n] - 2.f * acc[f][nt][2 * h];
                float d1 = sm + s_sqn[n + 1] - 2.f * acc[f][nt][2 * h + 1];
                bf16 v0 = d0 < 484.f ? one : zero;
                bf16 v1 = d1 < 484.f ? one : zero;
                cnt += (d0 < 484.f ? 1.f : 0.f) + (d1 < 484.f ? 1.f : 0.f);
                hrow[n >> 1] = pk2(v0, v1);
                if (mirror) {
                    tr[(size_t)n * 136 + m] = v0;
                    tr[(size_t)(n + 1) * 136 + m] = v1;
                }
            }
            cnt += __shfl_xor_sync(0xFFFFFFFFu, cnt, 1);
            cnt += __shfl_xor_sync(0xFFFFFFFFu, cnt, 2);
            if ((lane & 3) == 0) atomicAdd(&degb[m0 + m], cnt);
        }
    if (mirror) {
        __syncthreads();
        int r = t >> 1, half = t & 1;
        uint4* dst = (uint4*)(Hb + (size_t)(n0 + r) * ND + m0 + half * 64);
        const uint4* src = (const uint4*)(tr + (size_t)r * 136 + half * 64);
        float csum = 0.f;
#pragma unroll
        for (int k = 0; k < 8; k++) {
            uint4 v = src[k];
            dst[k] = v;
            uint32_t u[4] = {v.x, v.y, v.z, v.w};
#pragma unroll
            for (int q = 0; q < 4; q++) {
                float2 fv = __bfloat1622float2(*(__nv_bfloat162*)&u[q]);
                csum += fv.x + fv.y;
            }
        }
        atomicAdd(&degb[n0 + r], csum);
    }
}

// FC: xf_T[o][d] = sum_c W[o][c]*xt[d][c] + bias[o]
__global__ void __launch_bounds__(256, 2) k_fc_mma(const float* __restrict__ bias) {
    extern __shared__ char smem[];
    uint32_t sb = smem_u32(smem);
    int b = blockIdx.z, m0 = blockIdx.y * 128, n0 = blockIdx.x * 128;
    const bf16* Xh = g_xthi + (size_t)b * ND * NC;
    float acc[2][8][4] = {};
    gemm_main<1, 1, 3>(sb, g_whi + (size_t)m0 * NC, nullptr,
                       Xh + (size_t)n0 * NC, nullptr, NC, NC, NC / 64, acc);

    int t = threadIdx.x;
    int lane = t & 31, wid = t >> 5;
    int warp_m = (wid & 3) * 32, warp_n = (wid >> 2) * 64;
    int r4 = lane >> 2, c2 = (lane & 3) * 2;
#pragma unroll
    for (int f = 0; f < 2; f++)
#pragma unroll
        for (int h = 0; h < 2; h++) {
            int m = warp_m + f * 16 + r4 + h * 8;
            float bv = bias[m0 + m];
            uint32_t* rh = (uint32_t*)(g_xfhi + ((size_t)b * NC + m0 + m) * ND + n0);
#pragma unroll
            for (int nt = 0; nt < 8; nt++) {
                int n = warp_n + nt * 8 + c2;
                rh[n >> 1] = pk2(__float2bfloat16(acc[f][nt][2 * h] + bv),
                                 __float2bfloat16(acc[f][nt][2 * h + 1] + bv));
            }
        }
}

// AGG: D[o][n] = sum_k S[o][k]*hg[n][k]; scale by inv[n]; FINAL adds residual x.
template <bool FINAL>
__global__ void __launch_bounds__(256, 2) k_agg_mma(const float* __restrict__ xres,
                                                    float* __restrict__ out) {
    extern __shared__ char smem[];
    uint32_t sb = smem_u32(smem);
    int b = blockIdx.z, m0 = blockIdx.y * 128, n0 = blockIdx.x * 128;
    const bf16* Sh = (FINAL ? g_Ehi : g_xfhi) + (size_t)b * NC * ND;
    const bf16* H = g_hg + (size_t)b * ND * ND;
    float acc[2][8][4] = {};
    gemm_main<1, 1, 3>(sb, Sh + (size_t)m0 * ND, nullptr,
                       H + (size_t)n0 * ND, nullptr, ND, ND, ND / 64, acc);

    float* s_inv = (float*)smem;
    int t = threadIdx.x;
    if (t < 128) s_inv[t] = g_inv[b * ND + n0 + t];
    __syncthreads();

    int lane = t & 31, wid = t >> 5;
    int warp_m = (wid & 3) * 32, warp_n = (wid >> 2) * 64;
    int r4 = lane >> 2, c2 = (lane & 3) * 2;
#pragma unroll
    for (int f = 0; f < 2; f++)
#pragma unroll
        for (int h = 0; h < 2; h++) {
            int m = warp_m + f * 16 + r4 + h * 8;
            if (!FINAL) {
                uint32_t* rh = (uint32_t*)(g_Ehi + ((size_t)b * NC + m0 + m) * ND + n0);
#pragma unroll
                for (int nt = 0; nt < 8; nt++) {
                    int n = warp_n + nt * 8 + c2;
                    rh[n >> 1] = pk2(__float2bfloat16(acc[f][nt][2 * h] * s_inv[n]),
                                     __float2bfloat16(acc[f][nt][2 * h + 1] * s_inv[n + 1]));
                }
            } else {
                const float* xrow = xres + ((size_t)b * NC + m0 + m) * ND + n0;
                float* orow = out + ((size_t)b * NC + m0 + m) * ND + n0;
#pragma unroll
                for (int nt = 0; nt < 8; nt++) {
                    int n = warp_n + nt * 8 + c2;
                    float2 xv = *(const float2*)(xrow + n);
                    float2 o;
                    o.x = acc[f][nt][2 * h] * s_inv[n] + xv.x;
                    o.y = acc[f][nt][2 * h + 1] * s_inv[n + 1] + xv.y;
                    *(float2*)(orow + n) = o;
                }
            }
        }
}

// ---------------- prep / small kernels ----------------
__global__ void k_prep_xt(const float* __restrict__ x) {
    __shared__ float tile[32][33];
    int b = blockIdx.z;
    int d0 = blockIdx.x * 32, c0 = blockIdx.y * 32;
    const float* xb = x + (size_t)b * NC * ND;
    int tx = threadIdx.x, ty = threadIdx.y;  // 32x8
#pragma unroll
    for (int i = 0; i < 32; i += 8)
        tile[ty + i][tx] = xb[(size_t)(c0 + ty + i) * ND + d0 + tx];
    __syncthreads();
    bf16* oh = g_xthi + (size_t)b * ND * NC;
    bf16* ol = g_xtlo + (size_t)b * ND * NC;
#pragma unroll
    for (int i = 0; i < 32; i += 8) {
        float v = tile[tx][ty + i];
        bf16 h = __float2bfloat16(v);
        bf16 l = __float2bfloat16(v - __bfloat162float(h));
        size_t idx = (size_t)(d0 + ty + i) * NC + c0 + tx;
        oh[idx] = h;
        ol[idx] = l;
    }
}

__global__ void __launch_bounds__(256) k_sq(const float* __restrict__ x) {
    int gid = blockIdx.x * 256 + threadIdx.x;  // b*ND + d
    int b = gid >> 11, d = gid & (ND - 1);
    const float* xb = x + (size_t)b * NC * ND + d;
    float s = 0.f;
#pragma unroll 8
    for (int c = 0; c < NC; c++) {
        float v = xb[(size_t)c * ND];
        s += v * v;
    }
    g_sq[gid] = s;
    g_deg[gid] = 0.f;  // zero for gram's fused-degree atomics
}

__global__ void __launch_bounds__(256) k_prep_w(const float* __restrict__ W) {
    int i = blockIdx.x * 256 + threadIdx.x;
    g_whi[i] = __float2bfloat16(W[i]);
}

__global__ void __launch_bounds__(256) k_inv() {
    int gid = blockIdx.x * 256 + threadIdx.x;
    float d = g_deg[gid];
    g_inv[gid] = (d > 0.f) ? (1.f / d) : 0.f;
}

__global__ void __launch_bounds__(256) k_ln(float* __restrict__ out,
                                            const float* __restrict__ gamma,
                                            const float* __restrict__ beta) {
    int row = blockIdx.x;  // b*NC + c
    float* p = out + (size_t)row * ND;
    int t = threadIdx.x;
    float4 v0 = *(float4*)(p + t * 8);
    float4 v1 = *(float4*)(p + t * 8 + 4);
    float vals[8] = {v0.x, v0.y, v0.z, v0.w, v1.x, v1.y, v1.z, v1.w};
    float s = 0.f, s2 = 0.f;
#pragma unroll
    for (int u = 0; u < 8; u++) {
        s += vals[u];
        s2 += vals[u] * vals[u];
    }
    __shared__ float r1[256];
    __shared__ float r2[256];
    r1[t] = s;
    r2[t] = s2;
    __syncthreads();
    for (int o = 128; o > 0; o >>= 1) {
        if (t < o) {
            r1[t] += r1[t + o];
            r2[t] += r2[t + o];
        }
        __syncthreads();
    }
    float mean = r1[0] * (1.f / ND);
    float var = r2[0] * (1.f / ND) - mean * mean;
    float rstd = rsqrtf(var + 1e-5f);
#pragma unroll
    for (int u = 0; u < 8; u++) {
        int d = t * 8 + u;
        float yn = (vals[u] - mean) * rstd * gamma[d] + beta[d];
        vals[u] = yn / (1.f + expf(-yn));
    }
    v0.x = vals[0]; v0.y = vals[1]; v0.z = vals[2]; v0.w = vals[3];
    v1.x = vals[4]; v1.y = vals[5]; v1.z = vals[6]; v1.w = vals[7];
    *(float4*)(p + t * 8) = v0;
    *(float4*)(p + t * 8 + 4) = v1;
}

// ---------------- launch ----------------
extern "C" void kernel_launch(void* const* d_in, const int* in_sizes, int n_in,
                              void* d_out, int out_size) {
    const float* x = (const float*)d_in[0];
    const float* W = (const float*)d_in[1];
    const float* bias = (const float*)d_in[2];
    const float* gamma = (const float*)d_in[3];
    const float* beta = (const float*)d_in[4];
    float* out = (float*)d_out;
    (void)in_sizes; (void)n_in; (void)out_size;

    const int SMEM_GRAM = 3 * 4 * 16384;  // 196608 (3 stages x 4 tiles)
    const int SMEM_AGG = 3 * 2 * 16384;   // 98304  (3 stages x 2 tiles)
    static bool attr_set = false;
    if (!attr_set) {
        cudaFuncSetAttribute(k_gram_mma, cudaFuncAttributeMaxDynamicSharedMemorySize, SMEM_GRAM);
        cudaFuncSetAttribute(k_fc_mma, cudaFuncAttributeMaxDynamicSharedMemorySize, SMEM_AGG);
        cudaFuncSetAttribute(k_agg_mma<false>, cudaFuncAttributeMaxDynamicSharedMemorySize, SMEM_AGG);
        cudaFuncSetAttribute(k_agg_mma<true>, cudaFuncAttributeMaxDynamicSharedMemorySize, SMEM_AGG);
        attr_set = true;
    }

    const int NTRI = (ND / 128) * (ND / 128 + 1) / 2;  // 136

    k_prep_xt<<<dim3(ND / 32, NC / 32, NB), dim3(32, 8)>>>(x);
    k_sq<<<NB * ND / 256, 256>>>(x);
    k_prep_w<<<NC * NC / 256, 256>>>(W);
    k_gram_mma<<<dim3(NTRI, 1, NB), 256, SMEM_GRAM>>>();
    k_inv<<<NB * ND / 256, 256>>>();
    k_fc_mma<<<dim3(ND / 128, NC / 128, NB), 256, SMEM_AGG>>>(bias);
    k_agg_mma<false><<<dim3(ND / 128, NC / 128, NB), 256, SMEM_AGG>>>(nullptr, nullptr);
    k_agg_mma<true><<<dim3(ND / 128, NC / 128, NB), 256, SMEM_AGG>>>(x, out);
    k_ln<<<NB * NC, 256>>>(out, gamma, beta);
}

// round 9
// speedup vs baseline: 6.4690x; 1.0319x over previous
#include <cuda_runtime.h>
#include <cuda_bf16.h>
#include <cstdint>

#define NB 8
#define NC 256
#define ND 2048
typedef __nv_bfloat16 bf16;

// ---------------- static scratch ----------------
__device__ __align__(128) bf16  g_xthi[NB * ND * NC];
__device__ __align__(128) bf16  g_xtlo[NB * ND * NC];
__device__ __align__(128) float g_sq[NB * ND];
__device__ __align__(128) bf16  g_whi[NC * NC];
__device__ __align__(128) bf16  g_xfhi[NB * NC * ND];   // [b][o][d]
__device__ __align__(128) bf16  g_hg[(size_t)NB * ND * ND];
__device__ __align__(128) float g_deg[NB * ND];
__device__ __align__(128) float g_inv[NB * ND];
__device__ __align__(128) bf16  g_Ehi[NB * NC * ND];    // [b][o][d]

// ---------------- helpers ----------------
__device__ __forceinline__ uint32_t smem_u32(const void* p) {
    uint32_t a;
    asm("{ .reg .u64 t; cvta.to.shared.u64 t, %1; cvt.u32.u64 %0, t; }" : "=r"(a) : "l"(p));
    return a;
}
#define SW128(x) ((x) ^ (((x) >> 3) & 0x70))

// tile byte offset for logical row lr, byte-column bc, K-chunk CK (32 or 64)
template <int CK>
__device__ __forceinline__ uint32_t toff(int lr, int bc) {
    if (CK == 64) return SW128((uint32_t)(lr * 128 + bc));
    else          return SW128((uint32_t)(((lr >> 1) << 7) + ((lr & 1) << 6) + bc));
}

__device__ __forceinline__ void cp16(uint32_t dst, const void* src) {
    asm volatile("cp.async.cg.shared.global [%0], [%1], 16;\n" :: "r"(dst), "l"(src));
}
__device__ __forceinline__ void cpa_commit() { asm volatile("cp.async.commit_group;\n" ::: "memory"); }
template <int N>
__device__ __forceinline__ void cpa_waitN() { asm volatile("cp.async.wait_group %0;\n" :: "n"(N) : "memory"); }

__device__ __forceinline__ void ldm4(uint32_t* r, uint32_t addr) {
    asm volatile("ldmatrix.sync.aligned.m8n8.x4.shared.b16 {%0,%1,%2,%3}, [%4];"
                 : "=r"(r[0]), "=r"(r[1]), "=r"(r[2]), "=r"(r[3]) : "r"(addr));
}
__device__ __forceinline__ void mma16816(float* d, const uint32_t* a, const uint32_t* b) {
    asm volatile(
        "mma.sync.aligned.m16n8k16.row.col.f32.bf16.bf16.f32 "
        "{%0,%1,%2,%3}, {%4,%5,%6,%7}, {%8,%9}, {%0,%1,%2,%3};"
        : "+f"(d[0]), "+f"(d[1]), "+f"(d[2]), "+f"(d[3])
        : "r"(a[0]), "r"(a[1]), "r"(a[2]), "r"(a[3]), "r"(b[0]), "r"(b[1]));
}
__device__ __forceinline__ uint32_t pk2(bf16 a, bf16 b) {
    return (uint32_t)__bfloat16_as_ushort(a) | ((uint32_t)__bfloat16_as_ushort(b) << 16);
}

// load one 128-row x CK-col bf16 chunk into swizzled smem tile (256 threads)
template <int CK>
__device__ __forceinline__ void load_tile256(uint32_t tb, const bf16* g, size_t rs, int kc, int t) {
    const int SEGS = CK / 8;  // 16B segments per row
#pragma unroll
    for (int i = 0; i < CK / 16; i++) {
        int lin = i * 256 + t;
        int row = lin / SEGS, seg = lin % SEGS;
        cp16(tb + toff<CK>(row, seg * 16), g + (size_t)row * rs + kc + seg * 8);
    }
}

// ---------------- block GEMM mainloop ----------------
template <int NA, int NBt, int NSTAGES, int CK>
__device__ __forceinline__ void gemm_main(
    uint32_t sb, const bf16* A0, const bf16* A1, const bf16* B0, const bf16* B1,
    size_t sA, size_t sB, int nchunks, float acc[2][8][4])
{
    const uint32_t TS = 256u * CK;  // tile bytes
    const uint32_t STAGE = (NA + NBt) * TS;
    int t = threadIdx.x;
    int lane = t & 31, wid = t >> 5;
    int warp_m = (wid & 3) * 32, warp_n = (wid >> 2) * 64;
    int lrow = lane & 15;
    int lcol = (lane & 16) ? 16 : 0;

#pragma unroll
    for (int s = 0; s < NSTAGES - 1; s++) {
        uint32_t st = sb + (uint32_t)s * STAGE;
        int kc = s * CK;
        load_tile256<CK>(st + 0 * TS, A0, sA, kc, t);
        if (NA == 2) load_tile256<CK>(st + 1 * TS, A1, sA, kc, t);
        load_tile256<CK>(st + NA * TS, B0, sB, kc, t);
        if (NBt == 2) load_tile256<CK>(st + (NA + 1) * TS, B1, sB, kc, t);
        cpa_commit();
    }
    for (int c = 0; c < nchunks; c++) {
        uint32_t cur = sb + (uint32_t)(c % NSTAGES) * STAGE;
        int cn = c + NSTAGES - 1;
        if (cn < nchunks) {
            uint32_t nx = sb + (uint32_t)(cn % NSTAGES) * STAGE;
            int kc = cn * CK;
            load_tile256<CK>(nx + 0 * TS, A0, sA, kc, t);
            if (NA == 2) load_tile256<CK>(nx + 1 * TS, A1, sA, kc, t);
            load_tile256<CK>(nx + NA * TS, B0, sB, kc, t);
            if (NBt == 2) load_tile256<CK>(nx + (NA + 1) * TS, B1, sB, kc, t);
        }
        cpa_commit();
        cpa_waitN<NSTAGES - 1>();
        __syncthreads();
#pragma unroll
        for (int ks = 0; ks < CK / 16; ks++) {
            int kb = ks * 32 + lcol;
            uint32_t a[NA][2][4];
#pragma unroll
            for (int v = 0; v < NA; v++)
#pragma unroll
                for (int f = 0; f < 2; f++)
                    ldm4(a[v][f], cur + v * TS + toff<CK>(warp_m + f * 16 + lrow, kb));
            uint32_t bfr[NBt][8][2];
#pragma unroll
            for (int v = 0; v < NBt; v++)
#pragma unroll
                for (int np = 0; np < 4; np++) {
                    uint32_t r[4];
                    ldm4(r, cur + (NA + v) * TS + toff<CK>(warp_n + np * 16 + lrow, kb));
                    bfr[v][2 * np][0] = r[0]; bfr[v][2 * np][1] = r[2];
                    bfr[v][2 * np + 1][0] = r[1]; bfr[v][2 * np + 1][1] = r[3];
                }
#pragma unroll
            for (int pa = 0; pa < NA; pa++)
#pragma unroll
                for (int pb = 0; pb < NBt; pb++) {
                    if (pa == 1 && pb == 1) continue;
#pragma unroll
                    for (int f = 0; f < 2; f++)
#pragma unroll
                        for (int nt = 0; nt < 8; nt++)
                            mma16816(acc[f][nt], a[pa][f], bfr[pb][nt]);
                }
        }
        __syncthreads();
    }
}

// ---------------- GEMM kernels ----------------
// Gram + threshold + fused degree. Triangular grid: blockIdx.x in [0,136).
__global__ void __launch_bounds__(256, 2) k_gram_mma() {
    int L = blockIdx.x;
    int i = 0, rem = L;
    while (rem >= (ND / 128) - i) { rem -= (ND / 128) - i; i++; }
    int j = i + rem;

    extern __shared__ char smem[];
    uint32_t sb = smem_u32(smem);
    int b = blockIdx.z, m0 = i * 128, n0 = j * 128;
    const bf16* Xh = g_xthi + (size_t)b * ND * NC;
    const bf16* Xl = g_xtlo + (size_t)b * ND * NC;
    float acc[2][8][4] = {};
    gemm_main<2, 2, 3, 32>(sb, Xh + (size_t)m0 * NC, Xl + (size_t)m0 * NC,
                           Xh + (size_t)n0 * NC, Xl + (size_t)n0 * NC, NC, NC, NC / 32, acc);

    float* s_sqm = (float*)smem;
    float* s_sqn = s_sqm + 128;
    bf16* tr = (bf16*)(smem + 1024);  // [128][136] transpose staging
    int t = threadIdx.x;
    if (t < 128) s_sqm[t] = g_sq[b * ND + m0 + t];
    else s_sqn[t - 128] = g_sq[b * ND + n0 + (t - 128)];
    __syncthreads();

    int lane = t & 31, wid = t >> 5;
    int warp_m = (wid & 3) * 32, warp_n = (wid >> 2) * 64;
    int r4 = lane >> 2, c2 = (lane & 3) * 2;
    bf16* Hb = g_hg + (size_t)b * ND * ND;
    float* degb = g_deg + b * ND;
    const bf16 one = __float2bfloat16(1.f), zero = __float2bfloat16(0.f);
    bool mirror = (j > i);
#pragma unroll
    for (int f = 0; f < 2; f++)
#pragma unroll
        for (int h = 0; h < 2; h++) {
            int m = warp_m + f * 16 + r4 + h * 8;
            float sm = s_sqm[m];
            uint32_t* hrow = (uint32_t*)(Hb + (size_t)(m0 + m) * ND + n0);
            float cnt = 0.f;
#pragma unroll
            for (int nt = 0; nt < 8; nt++) {
                int n = warp_n + nt * 8 + c2;
                float d0 = sm + s_sqn[n] - 2.f * acc[f][nt][2 * h];
                float d1 = sm + s_sqn[n + 1] - 2.f * acc[f][nt][2 * h + 1];
                bf16 v0 = d0 < 484.f ? one : zero;
                bf16 v1 = d1 < 484.f ? one : zero;
                cnt += (d0 < 484.f ? 1.f : 0.f) + (d1 < 484.f ? 1.f : 0.f);
                hrow[n >> 1] = pk2(v0, v1);
                if (mirror) {
                    tr[(size_t)n * 136 + m] = v0;
                    tr[(size_t)(n + 1) * 136 + m] = v1;
                }
            }
            cnt += __shfl_xor_sync(0xFFFFFFFFu, cnt, 1);
            cnt += __shfl_xor_sync(0xFFFFFFFFu, cnt, 2);
            if ((lane & 3) == 0) atomicAdd(&degb[m0 + m], cnt);
        }
    if (mirror) {
        __syncthreads();
        int r = t >> 1, half = t & 1;
        uint4* dst = (uint4*)(Hb + (size_t)(n0 + r) * ND + m0 + half * 64);
        const uint4* src = (const uint4*)(tr + (size_t)r * 136 + half * 64);
        float csum = 0.f;
#pragma unroll
        for (int k = 0; k < 8; k++) {
            uint4 v = src[k];
            dst[k] = v;
            uint32_t u[4] = {v.x, v.y, v.z, v.w};
#pragma unroll
            for (int q = 0; q < 4; q++) {
                float2 fv = __bfloat1622float2(*(__nv_bfloat162*)&u[q]);
                csum += fv.x + fv.y;
            }
        }
        atomicAdd(&degb[n0 + r], csum);
    }
}

// FC: xf_T[o][d] = sum_c W[o][c]*xt[d][c] + bias[o]
__global__ void __launch_bounds__(256, 2) k_fc_mma(const float* __restrict__ bias) {
    extern __shared__ char smem[];
    uint32_t sb = smem_u32(smem);
    int b = blockIdx.z, m0 = blockIdx.y * 128, n0 = blockIdx.x * 128;
    const bf16* Xh = g_xthi + (size_t)b * ND * NC;
    float acc[2][8][4] = {};
    gemm_main<1, 1, 3, 64>(sb, g_whi + (size_t)m0 * NC, nullptr,
                           Xh + (size_t)n0 * NC, nullptr, NC, NC, NC / 64, acc);

    int t = threadIdx.x;
    int lane = t & 31, wid = t >> 5;
    int warp_m = (wid & 3) * 32, warp_n = (wid >> 2) * 64;
    int r4 = lane >> 2, c2 = (lane & 3) * 2;
#pragma unroll
    for (int f = 0; f < 2; f++)
#pragma unroll
        for (int h = 0; h < 2; h++) {
            int m = warp_m + f * 16 + r4 + h * 8;
            float bv = bias[m0 + m];
            uint32_t* rh = (uint32_t*)(g_xfhi + ((size_t)b * NC + m0 + m) * ND + n0);
#pragma unroll
            for (int nt = 0; nt < 8; nt++) {
                int n = warp_n + nt * 8 + c2;
                rh[n >> 1] = pk2(__float2bfloat16(acc[f][nt][2 * h] + bv),
                                 __float2bfloat16(acc[f][nt][2 * h + 1] + bv));
            }
        }
}

// AGG: D[o][n] = sum_k S[o][k]*hg[n][k]; scale by inv[n]; FINAL adds residual x.
template <bool FINAL>
__global__ void __launch_bounds__(256, 2) k_agg_mma(const float* __restrict__ xres,
                                                    float* __restrict__ out) {
    extern __shared__ char smem[];
    uint32_t sb = smem_u32(smem);
    int b = blockIdx.z, m0 = blockIdx.y * 128, n0 = blockIdx.x * 128;
    const bf16* Sh = (FINAL ? g_Ehi : g_xfhi) + (size_t)b * NC * ND;
    const bf16* H = g_hg + (size_t)b * ND * ND;
    float acc[2][8][4] = {};
    gemm_main<1, 1, 3, 64>(sb, Sh + (size_t)m0 * ND, nullptr,
                           H + (size_t)n0 * ND, nullptr, ND, ND, ND / 64, acc);

    float* s_inv = (float*)smem;
    int t = threadIdx.x;
    if (t < 128) s_inv[t] = g_inv[b * ND + n0 + t];
    __syncthreads();

    int lane = t & 31, wid = t >> 5;
    int warp_m = (wid & 3) * 32, warp_n = (wid >> 2) * 64;
    int r4 = lane >> 2, c2 = (lane & 3) * 2;
#pragma unroll
    for (int f = 0; f < 2; f++)
#pragma unroll
        for (int h = 0; h < 2; h++) {
            int m = warp_m + f * 16 + r4 + h * 8;
            if (!FINAL) {
                uint32_t* rh = (uint32_t*)(g_Ehi + ((size_t)b * NC + m0 + m) * ND + n0);
#pragma unroll
                for (int nt = 0; nt < 8; nt++) {
                    int n = warp_n + nt * 8 + c2;
                    rh[n >> 1] = pk2(__float2bfloat16(acc[f][nt][2 * h] * s_inv[n]),
                                     __float2bfloat16(acc[f][nt][2 * h + 1] * s_inv[n + 1]));
                }
            } else {
                const float* xrow = xres + ((size_t)b * NC + m0 + m) * ND + n0;
                float* orow = out + ((size_t)b * NC + m0 + m) * ND + n0;
#pragma unroll
                for (int nt = 0; nt < 8; nt++) {
                    int n = warp_n + nt * 8 + c2;
                    float2 xv = *(const float2*)(xrow + n);
                    float2 o;
                    o.x = acc[f][nt][2 * h] * s_inv[n] + xv.x;
                    o.y = acc[f][nt][2 * h + 1] * s_inv[n + 1] + xv.y;
                    *(float2*)(orow + n) = o;
                }
            }
        }
}

// ---------------- prep / small kernels ----------------
__global__ void k_prep_xt(const float* __restrict__ x) {
    __shared__ float tile[32][33];
    int b = blockIdx.z;
    int d0 = blockIdx.x * 32, c0 = blockIdx.y * 32;
    const float* xb = x + (size_t)b * NC * ND;
    int tx = threadIdx.x, ty = threadIdx.y;  // 32x8
#pragma unroll
    for (int i = 0; i < 32; i += 8)
        tile[ty + i][tx] = xb[(size_t)(c0 + ty + i) * ND + d0 + tx];
    __syncthreads();
    bf16* oh = g_xthi + (size_t)b * ND * NC;
    bf16* ol = g_xtlo + (size_t)b * ND * NC;
#pragma unroll
    for (int i = 0; i < 32; i += 8) {
        float v = tile[tx][ty + i];
        bf16 h = __float2bfloat16(v);
        bf16 l = __float2bfloat16(v - __bfloat162float(h));
        size_t idx = (size_t)(d0 + ty + i) * NC + c0 + tx;
        oh[idx] = h;
        ol[idx] = l;
    }
}

__global__ void __launch_bounds__(256) k_sq(const float* __restrict__ x) {
    int gid = blockIdx.x * 256 + threadIdx.x;  // b*ND + d
    int b = gid >> 11, d = gid & (ND - 1);
    const float* xb = x + (size_t)b * NC * ND + d;
    float s = 0.f;
#pragma unroll 8
    for (int c = 0; c < NC; c++) {
        float v = xb[(size_t)c * ND];
        s += v * v;
    }
    g_sq[gid] = s;
    g_deg[gid] = 0.f;  // zero for gram's fused-degree atomics
}

__global__ void __launch_bounds__(256) k_prep_w(const float* __restrict__ W) {
    int i = blockIdx.x * 256 + threadIdx.x;
    g_whi[i] = __float2bfloat16(W[i]);
}

__global__ void __launch_bounds__(256) k_inv() {
    int gid = blockIdx.x * 256 + threadIdx.x;
    float d = g_deg[gid];
    g_inv[gid] = (d > 0.f) ? (1.f / d) : 0.f;
}

__global__ void __launch_bounds__(256) k_ln(float* __restrict__ out,
                                            const float* __restrict__ gamma,
                                            const float* __restrict__ beta) {
    int row = blockIdx.x;  // b*NC + c
    float* p = out + (size_t)row * ND;
    int t = threadIdx.x;
    float4 v0 = *(float4*)(p + t * 8);
    float4 v1 = *(float4*)(p + t * 8 + 4);
    float vals[8] = {v0.x, v0.y, v0.z, v0.w, v1.x, v1.y, v1.z, v1.w};
    float s = 0.f, s2 = 0.f;
#pragma unroll
    for (int u = 0; u < 8; u++) {
        s += vals[u];
        s2 += vals[u] * vals[u];
    }
    __shared__ float r1[256];
    __shared__ float r2[256];
    r1[t] = s;
    r2[t] = s2;
    __syncthreads();
    for (int o = 128; o > 0; o >>= 1) {
        if (t < o) {
            r1[t] += r1[t + o];
            r2[t] += r2[t + o];
        }
        __syncthreads();
    }
    float mean = r1[0] * (1.f / ND);
    float var = r2[0] * (1.f / ND) - mean * mean;
    float rstd = rsqrtf(var + 1e-5f);
#pragma unroll
    for (int u = 0; u < 8; u++) {
        int d = t * 8 + u;
        float yn = (vals[u] - mean) * rstd * gamma[d] + beta[d];
        vals[u] = yn / (1.f + expf(-yn));
    }
    v0.x = vals[0]; v0.y = vals[1]; v0.z = vals[2]; v0.w = vals[3];
    v1.x = vals[4]; v1.y = vals[5]; v1.z = vals[6]; v1.w = vals[7];
    *(float4*)(p + t * 8) = v0;
    *(float4*)(p + t * 8 + 4) = v1;
}

// ---------------- launch ----------------
extern "C" void kernel_launch(void* const* d_in, const int* in_sizes, int n_in,
                              void* d_out, int out_size) {
    const float* x = (const float*)d_in[0];
    const float* W = (const float*)d_in[1];
    const float* bias = (const float*)d_in[2];
    const float* gamma = (const float*)d_in[3];
    const float* beta = (const float*)d_in[4];
    float* out = (float*)d_out;
    (void)in_sizes; (void)n_in; (void)out_size;

    const int SMEM_GRAM = 3 * 4 * 8192;  // 98304 (3 stages x 4 K32-tiles)
    const int SMEM_AGG = 3 * 2 * 16384;  // 98304 (3 stages x 2 K64-tiles)
    static bool attr_set = false;
    if (!attr_set) {
        cudaFuncSetAttribute(k_gram_mma, cudaFuncAttributeMaxDynamicSharedMemorySize, SMEM_GRAM);
        cudaFuncSetAttribute(k_fc_mma, cudaFuncAttributeMaxDynamicSharedMemorySize, SMEM_AGG);
        cudaFuncSetAttribute(k_agg_mma<false>, cudaFuncAttributeMaxDynamicSharedMemorySize, SMEM_AGG);
        cudaFuncSetAttribute(k_agg_mma<true>, cudaFuncAttributeMaxDynamicSharedMemorySize, SMEM_AGG);
        attr_set = true;
    }

    const int NTRI = (ND / 128) * (ND / 128 + 1) / 2;  // 136

    k_prep_xt<<<dim3(ND / 32, NC / 32, NB), dim3(32, 8)>>>(x);
    k_sq<<<NB * ND / 256, 256>>>(x);
    k_prep_w<<<NC * NC / 256, 256>>>(W);
    k_gram_mma<<<dim3(NTRI, 1, NB), 256, SMEM_GRAM>>>();
    k_inv<<<NB * ND / 256, 256>>>();
    k_fc_mma<<<dim3(ND / 128, NC / 128, NB), 256, SMEM_AGG>>>(bias);
    k_agg_mma<false><<<dim3(ND / 128, NC / 128, NB), 256, SMEM_AGG>>>(nullptr, nullptr);
    k_agg_mma<true><<<dim3(ND / 128, NC / 128, NB), 256, SMEM_AGG>>>(x, out);
    k_ln<<<NB * NC, 256>>>(out, gamma, beta);
}

// round 10
// speedup vs baseline: 7.9931x; 1.2356x over previous
#include <cuda_runtime.h>
#include <cuda_fp16.h>
#include <cstdint>

#define NB 8
#define NC 256
#define ND 2048
typedef __half fp16;

// ---------------- static scratch ----------------
__device__ __align__(128) fp16  g_xt[NB * ND * NC];
__device__ __align__(128) float g_sq[NB * ND];
__device__ __align__(128) fp16  g_w[NC * NC];
__device__ __align__(128) fp16  g_xf[NB * NC * ND];    // [b][o][d]
__device__ __align__(128) fp16  g_hg[(size_t)NB * ND * ND];
__device__ __align__(128) float g_deg[NB * ND];
__device__ __align__(128) float g_inv[NB * ND];
__device__ __align__(128) fp16  g_E[NB * NC * ND];     // [b][o][d]

// ---------------- helpers ----------------
__device__ __forceinline__ uint32_t smem_u32(const void* p) {
    uint32_t a;
    asm("{ .reg .u64 t; cvta.to.shared.u64 t, %1; cvt.u32.u64 %0, t; }" : "=r"(a) : "l"(p));
    return a;
}
#define SW128(x) ((x) ^ (((x) >> 3) & 0x70))

__device__ __forceinline__ void cp16(uint32_t dst, const void* src) {
    asm volatile("cp.async.cg.shared.global [%0], [%1], 16;\n" :: "r"(dst), "l"(src));
}
__device__ __forceinline__ void cpa_commit() { asm volatile("cp.async.commit_group;\n" ::: "memory"); }
template <int N>
__device__ __forceinline__ void cpa_waitN() { asm volatile("cp.async.wait_group %0;\n" :: "n"(N) : "memory"); }

__device__ __forceinline__ void ldm4(uint32_t* r, uint32_t addr) {
    asm volatile("ldmatrix.sync.aligned.m8n8.x4.shared.b16 {%0,%1,%2,%3}, [%4];"
                 : "=r"(r[0]), "=r"(r[1]), "=r"(r[2]), "=r"(r[3]) : "r"(addr));
}
__device__ __forceinline__ void mma16816(float* d, const uint32_t* a, const uint32_t* b) {
    asm volatile(
        "mma.sync.aligned.m16n8k16.row.col.f32.f16.f16.f32 "
        "{%0,%1,%2,%3}, {%4,%5,%6,%7}, {%8,%9}, {%0,%1,%2,%3};"
        : "+f"(d[0]), "+f"(d[1]), "+f"(d[2]), "+f"(d[3])
        : "r"(a[0]), "r"(a[1]), "r"(a[2]), "r"(a[3]), "r"(b[0]), "r"(b[1]));
}
__device__ __forceinline__ uint32_t pk2(fp16 a, fp16 b) {
    return (uint32_t)__half_as_ushort(a) | ((uint32_t)__half_as_ushort(b) << 16);
}

// load one 128-row x 64-col fp16 chunk into SW128 smem tile (256 threads)
__device__ __forceinline__ void load_tile256(uint32_t tb, const fp16* g, size_t rs, int kc, int t) {
#pragma unroll
    for (int i = 0; i < 4; i++) {
        int lin = i * 256 + t;
        int row = lin >> 3, seg = lin & 7;
        cp16(tb + SW128((uint32_t)(row * 128 + seg * 16)), g + (size_t)row * rs + kc + seg * 8);
    }
}

// ---------------- block GEMM mainloop (1 A tile, 1 B tile, K64 chunks) ----------------
template <int NSTAGES>
__device__ __forceinline__ void gemm_main(
    uint32_t sb, const fp16* A0, const fp16* B0,
    size_t sA, size_t sB, int nchunks, float acc[2][8][4])
{
    const uint32_t TS = 16384u;
    const uint32_t STAGE = 2 * TS;
    int t = threadIdx.x;
    int lane = t & 31, wid = t >> 5;
    int warp_m = (wid & 3) * 32, warp_n = (wid >> 2) * 64;
    int lrow = lane & 15;
    int lcol = (lane & 16) ? 16 : 0;

#pragma unroll
    for (int s = 0; s < NSTAGES - 1; s++) {
        uint32_t st = sb + (uint32_t)s * STAGE;
        int kc = s * 64;
        load_tile256(st, A0, sA, kc, t);
        load_tile256(st + TS, B0, sB, kc, t);
        cpa_commit();
    }
    for (int c = 0; c < nchunks; c++) {
        uint32_t cur = sb + (uint32_t)(c % NSTAGES) * STAGE;
        int cn = c + NSTAGES - 1;
        if (cn < nchunks) {
            uint32_t nx = sb + (uint32_t)(cn % NSTAGES) * STAGE;
            int kc = cn * 64;
            load_tile256(nx, A0, sA, kc, t);
            load_tile256(nx + TS, B0, sB, kc, t);
        }
        cpa_commit();
        cpa_waitN<NSTAGES - 1>();
        __syncthreads();
#pragma unroll
        for (int ks = 0; ks < 4; ks++) {
            int kb = ks * 32 + lcol;
            uint32_t a[2][4];
#pragma unroll
            for (int f = 0; f < 2; f++)
                ldm4(a[f], cur + SW128((uint32_t)((warp_m + f * 16 + lrow) * 128 + kb)));
            uint32_t bfr[8][2];
#pragma unroll
            for (int np = 0; np < 4; np++) {
                uint32_t r[4];
                ldm4(r, cur + TS + SW128((uint32_t)((warp_n + np * 16 + lrow) * 128 + kb)));
                bfr[2 * np][0] = r[0]; bfr[2 * np][1] = r[2];
                bfr[2 * np + 1][0] = r[1]; bfr[2 * np + 1][1] = r[3];
            }
#pragma unroll
            for (int f = 0; f < 2; f++)
#pragma unroll
                for (int nt = 0; nt < 8; nt++)
                    mma16816(acc[f][nt], a[f], bfr[nt]);
        }
        __syncthreads();
    }
}

// ---------------- GEMM kernels ----------------
// Gram + threshold + fused degree. Triangular grid: blockIdx.x in [0,136).
__global__ void __launch_bounds__(256, 2) k_gram_mma() {
    int L = blockIdx.x;
    int i = 0, rem = L;
    while (rem >= (ND / 128) - i) { rem -= (ND / 128) - i; i++; }
    int j = i + rem;

    extern __shared__ char smem[];
    uint32_t sb = smem_u32(smem);
    int b = blockIdx.z, m0 = i * 128, n0 = j * 128;
    const fp16* X = g_xt + (size_t)b * ND * NC;
    float acc[2][8][4] = {};
    gemm_main<3>(sb, X + (size_t)m0 * NC, X + (size_t)n0 * NC, NC, NC, NC / 64, acc);

    float* s_sqm = (float*)smem;
    float* s_sqn = s_sqm + 128;
    fp16* tr = (fp16*)(smem + 1024);  // [128][136] transpose staging
    int t = threadIdx.x;
    if (t < 128) s_sqm[t] = g_sq[b * ND + m0 + t];
    else s_sqn[t - 128] = g_sq[b * ND + n0 + (t - 128)];
    __syncthreads();

    int lane = t & 31, wid = t >> 5;
    int warp_m = (wid & 3) * 32, warp_n = (wid >> 2) * 64;
    int r4 = lane >> 2, c2 = (lane & 3) * 2;
    fp16* Hb = g_hg + (size_t)b * ND * ND;
    float* degb = g_deg + b * ND;
    const fp16 one = __float2half_rn(1.f), zero = __float2half_rn(0.f);
    bool mirror = (j > i);
#pragma unroll
    for (int f = 0; f < 2; f++)
#pragma unroll
        for (int h = 0; h < 2; h++) {
            int m = warp_m + f * 16 + r4 + h * 8;
            float sm = s_sqm[m];
            uint32_t* hrow = (uint32_t*)(Hb + (size_t)(m0 + m) * ND + n0);
            float cnt = 0.f;
#pragma unroll
            for (int nt = 0; nt < 8; nt++) {
                int n = warp_n + nt * 8 + c2;
                float d0 = sm + s_sqn[n] - 2.f * acc[f][nt][2 * h];
                float d1 = sm + s_sqn[n + 1] - 2.f * acc[f][nt][2 * h + 1];
                fp16 v0 = d0 < 484.f ? one : zero;
                fp16 v1 = d1 < 484.f ? one : zero;
                cnt += (d0 < 484.f ? 1.f : 0.f) + (d1 < 484.f ? 1.f : 0.f);
                hrow[n >> 1] = pk2(v0, v1);
                if (mirror) {
                    tr[(size_t)n * 136 + m] = v0;
                    tr[(size_t)(n + 1) * 136 + m] = v1;
                }
            }
            cnt += __shfl_xor_sync(0xFFFFFFFFu, cnt, 1);
            cnt += __shfl_xor_sync(0xFFFFFFFFu, cnt, 2);
            if ((lane & 3) == 0) atomicAdd(&degb[m0 + m], cnt);
        }
    if (mirror) {
        __syncthreads();
        int r = t >> 1, half = t & 1;
        uint4* dst = (uint4*)(Hb + (size_t)(n0 + r) * ND + m0 + half * 64);
        const uint4* src = (const uint4*)(tr + (size_t)r * 136 + half * 64);
        float csum = 0.f;
#pragma unroll
        for (int k = 0; k < 8; k++) {
            uint4 v = src[k];
            dst[k] = v;
            uint32_t u[4] = {v.x, v.y, v.z, v.w};
#pragma unroll
            for (int q = 0; q < 4; q++) {
                float2 fv = __half22float2(*(half2*)&u[q]);
                csum += fv.x + fv.y;
            }
        }
        atomicAdd(&degb[n0 + r], csum);
    }
}

// FC: xf_T[o][d] = sum_c W[o][c]*xt[d][c] + bias[o]
__global__ void __launch_bounds__(256, 2) k_fc_mma(const float* __restrict__ bias) {
    extern __shared__ char smem[];
    uint32_t sb = smem_u32(smem);
    int b = blockIdx.z, m0 = blockIdx.y * 128, n0 = blockIdx.x * 128;
    const fp16* X = g_xt + (size_t)b * ND * NC;
    float acc[2][8][4] = {};
    gemm_main<3>(sb, g_w + (size_t)m0 * NC, X + (size_t)n0 * NC, NC, NC, NC / 64, acc);

    int t = threadIdx.x;
    int lane = t & 31, wid = t >> 5;
    int warp_m = (wid & 3) * 32, warp_n = (wid >> 2) * 64;
    int r4 = lane >> 2, c2 = (lane & 3) * 2;
#pragma unroll
    for (int f = 0; f < 2; f++)
#pragma unroll
        for (int h = 0; h < 2; h++) {
            int m = warp_m + f * 16 + r4 + h * 8;
            float bv = bias[m0 + m];
            uint32_t* rh = (uint32_t*)(g_xf + ((size_t)b * NC + m0 + m) * ND + n0);
#pragma unroll
            for (int nt = 0; nt < 8; nt++) {
                int n = warp_n + nt * 8 + c2;
                rh[n >> 1] = pk2(__float2half_rn(acc[f][nt][2 * h] + bv),
                                 __float2half_rn(acc[f][nt][2 * h + 1] + bv));
            }
        }
}

// AGG: D[o][n] = sum_k S[o][k]*hg[n][k]; scale by inv[n]; FINAL adds residual x.
template <bool FINAL>
__global__ void __launch_bounds__(256, 2) k_agg_mma(const float* __restrict__ xres,
                                                    float* __restrict__ out) {
    extern __shared__ char smem[];
    uint32_t sb = smem_u32(smem);
    int b = blockIdx.z, m0 = blockIdx.y * 128, n0 = blockIdx.x * 128;
    const fp16* S = (FINAL ? g_E : g_xf) + (size_t)b * NC * ND;
    const fp16* H = g_hg + (size_t)b * ND * ND;
    float acc[2][8][4] = {};
    gemm_main<3>(sb, S + (size_t)m0 * ND, H + (size_t)n0 * ND, ND, ND, ND / 64, acc);

    float* s_inv = (float*)smem;
    int t = threadIdx.x;
    if (t < 128) s_inv[t] = g_inv[b * ND + n0 + t];
    __syncthreads();

    int lane = t & 31, wid = t >> 5;
    int warp_m = (wid & 3) * 32, warp_n = (wid >> 2) * 64;
    int r4 = lane >> 2, c2 = (lane & 3) * 2;
#pragma unroll
    for (int f = 0; f < 2; f++)
#pragma unroll
        for (int h = 0; h < 2; h++) {
            int m = warp_m + f * 16 + r4 + h * 8;
            if (!FINAL) {
                uint32_t* rh = (uint32_t*)(g_E + ((size_t)b * NC + m0 + m) * ND + n0);
#pragma unroll
                for (int nt = 0; nt < 8; nt++) {
                    int n = warp_n + nt * 8 + c2;
                    rh[n >> 1] = pk2(__float2half_rn(acc[f][nt][2 * h] * s_inv[n]),
                                     __float2half_rn(acc[f][nt][2 * h + 1] * s_inv[n + 1]));
                }
            } else {
                const float* xrow = xres + ((size_t)b * NC + m0 + m) * ND + n0;
                float* orow = out + ((size_t)b * NC + m0 + m) * ND + n0;
#pragma unroll
                for (int nt = 0; nt < 8; nt++) {
                    int n = warp_n + nt * 8 + c2;
                    float2 xv = *(const float2*)(xrow + n);
                    float2 o;
                    o.x = acc[f][nt][2 * h] * s_inv[n] + xv.x;
                    o.y = acc[f][nt][2 * h + 1] * s_inv[n + 1] + xv.y;
                    *(float2*)(orow + n) = o;
                }
            }
        }
}

// ---------------- prep / small kernels ----------------
__global__ void k_prep_xt(const float* __restrict__ x) {
    __shared__ float tile[32][33];
    int b = blockIdx.z;
    int d0 = blockIdx.x * 32, c0 = blockIdx.y * 32;
    const float* xb = x + (size_t)b * NC * ND;
    int tx = threadIdx.x, ty = threadIdx.y;  // 32x8
#pragma unroll
    for (int i = 0; i < 32; i += 8)
        tile[ty + i][tx] = xb[(size_t)(c0 + ty + i) * ND + d0 + tx];
    __syncthreads();
    fp16* oh = g_xt + (size_t)b * ND * NC;
#pragma unroll
    for (int i = 0; i < 32; i += 8)
        oh[(size_t)(d0 + ty + i) * NC + c0 + tx] = __float2half_rn(tile[tx][ty + i]);
}

__global__ void __launch_bounds__(256) k_sq(const float* __restrict__ x) {
    int gid = blockIdx.x * 256 + threadIdx.x;  // b*ND + d
    int b = gid >> 11, d = gid & (ND - 1);
    const float* xb = x + (size_t)b * NC * ND + d;
    float s = 0.f;
#pragma unroll 8
    for (int c = 0; c < NC; c++) {
        float v = xb[(size_t)c * ND];
        s += v * v;
    }
    g_sq[gid] = s;
    g_deg[gid] = 0.f;  // zero for gram's fused-degree atomics
}

__global__ void __launch_bounds__(256) k_prep_w(const float* __restrict__ W) {
    int i = blockIdx.x * 256 + threadIdx.x;
    g_w[i] = __float2half_rn(W[i]);
}

__global__ void __launch_bounds__(256) k_inv() {
    int gid = blockIdx.x * 256 + threadIdx.x;
    float d = g_deg[gid];
    g_inv[gid] = (d > 0.f) ? (1.f / d) : 0.f;
}

__global__ void __launch_bounds__(256) k_ln(float* __restrict__ out,
                                            const float* __restrict__ gamma,
                                            const float* __restrict__ beta) {
    int row = blockIdx.x;  // b*NC + c
    float* p = out + (size_t)row * ND;
    int t = threadIdx.x;
    float4 v0 = *(float4*)(p + t * 8);
    float4 v1 = *(float4*)(p + t * 8 + 4);
    float vals[8] = {v0.x, v0.y, v0.z, v0.w, v1.x, v1.y, v1.z, v1.w};
    float s = 0.f, s2 = 0.f;
#pragma unroll
    for (int u = 0; u < 8; u++) {
        s += vals[u];
        s2 += vals[u] * vals[u];
    }
    __shared__ float r1[256];
    __shared__ float r2[256];
    r1[t] = s;
    r2[t] = s2;
    __syncthreads();
    for (int o = 128; o > 0; o >>= 1) {
        if (t < o) {
            r1[t] += r1[t + o];
            r2[t] += r2[t + o];
        }
        __syncthreads();
    }
    float mean = r1[0] * (1.f / ND);
    float var = r2[0] * (1.f / ND) - mean * mean;
    float rstd = rsqrtf(var + 1e-5f);
#pragma unroll
    for (int u = 0; u < 8; u++) {
        int d = t * 8 + u;
        float yn = (vals[u] - mean) * rstd * gamma[d] + beta[d];
        vals[u] = yn / (1.f + expf(-yn));
    }
    v0.x = vals[0]; v0.y = vals[1]; v0.z = vals[2]; v0.w = vals[3];
    v1.x = vals[4]; v1.y = vals[5]; v1.z = vals[6]; v1.w = vals[7];
    *(float4*)(p + t * 8) = v0;
    *(float4*)(p + t * 8 + 4) = v1;
}

// ---------------- launch ----------------
extern "C" void kernel_launch(void* const* d_in, const int* in_sizes, int n_in,
                              void* d_out, int out_size) {
    const float* x = (const float*)d_in[0];
    const float* W = (const float*)d_in[1];
    const float* bias = (const float*)d_in[2];
    const float* gamma = (const float*)d_in[3];
    const float* beta = (const float*)d_in[4];
    float* out = (float*)d_out;
    (void)in_sizes; (void)n_in; (void)out_size;

    const int SMEM_G = 3 * 2 * 16384;  // 98304 (3 stages x 2 K64-tiles) — all GEMMs
    static bool attr_set = false;
    if (!attr_set) {
        cudaFuncSetAttribute(k_gram_mma, cudaFuncAttributeMaxDynamicSharedMemorySize, SMEM_G);
        cudaFuncSetAttribute(k_fc_mma, cudaFuncAttributeMaxDynamicSharedMemorySize, SMEM_G);
        cudaFuncSetAttribute(k_agg_mma<false>, cudaFuncAttributeMaxDynamicSharedMemorySize, SMEM_G);
        cudaFuncSetAttribute(k_agg_mma<true>, cudaFuncAttributeMaxDynamicSharedMemorySize, SMEM_G);
        attr_set = true;
    }

    const int NTRI = (ND / 128) * (ND / 128 + 1) / 2;  // 136

    k_prep_xt<<<dim3(ND / 32, NC / 32, NB), dim3(32, 8)>>>(x);
    k_sq<<<NB * ND / 256, 256>>>(x);
    k_prep_w<<<NC * NC / 256, 256>>>(W);
    k_gram_mma<<<dim3(NTRI, 1, NB), 256, SMEM_G>>>();
    k_inv<<<NB * ND / 256, 256>>>();
    k_fc_mma<<<dim3(ND / 128, NC / 128, NB), 256, SMEM_G>>>(bias);
    k_agg_mma<false><<<dim3(ND / 128, NC / 128, NB), 256, SMEM_G>>>(nullptr, nullptr);
    k_agg_mma<true><<<dim3(ND / 128, NC / 128, NB), 256, SMEM_G>>>(x, out);
    k_ln<<<NB * NC, 256>>>(out, gamma, beta);
}